// round 9
// baseline (speedup 1.0000x reference)
#include <cuda_runtime.h>
#include <math.h>
#include <stdint.h>

// ---------------- problem constants ----------------
#define NN    30000
#define EE    300000
#define FIN   33
#define HID   132
#define HEADS 4
#define HH    528
#define GG    64
#define GFC   1024
#define OUTD  128
#define NPAD  144

// ---------------- scratch (device globals) ----------------
__device__ __align__(16) float g_dis[NN];
__device__ int   g_cnt[NN];
__device__ int   g_off[NN+1];
__device__ int   g_cur[NN];
__device__ int   g_csr_src[EE];
__device__ int   g_csr_eid[EE];
__device__ __align__(16) float g_h0[NN*HID];
__device__ __align__(16) float g_x1[NN*HID];
__device__ __align__(16) float g_x2[NN*HID];
__device__ __align__(16) float g_Z[NN*HH];
__device__ __align__(16) float g_es[NN*HEADS];
__device__ __align__(16) float g_ed[NN*HEADS];
__device__ __align__(16) float g_xc[NN*HID];
__device__ unsigned g_pool_u[GG*HID];
__device__ __align__(16) float g_pool[GG*HID];
__device__ __align__(16) float g_hid[GG*GFC];
__device__ __align__(16) float g_wesd1[HID*8];
__device__ __align__(16) float g_wesd2[HID*8];
// fp32 prepped weights, [NPAD][K] (n-major, k contiguous)
__device__ __align__(16) float g_wgcn[NPAD*FIN];
__device__ __align__(16) float g_ws1[NPAD*HH];
__device__ __align__(16) float g_ws2[NPAD*HH];
__device__ __align__(16) float g_wfc[NPAD*264];
__device__ float g_bias_fc[HID];

// ---------------- CSR build ----------------
__global__ void zero_cnt_pool_kernel() {
    int i = blockIdx.x*blockDim.x + threadIdx.x;
    if (i < NN) g_cnt[i] = 0;
    if (i < GG*HID) g_pool_u[i] = 0u;
}
__global__ void hist_kernel(const int* __restrict__ ei) {
    int e = blockIdx.x*blockDim.x + threadIdx.x;
    if (e < EE) atomicAdd(&g_cnt[ei[EE + e]], 1);
}
__global__ void scan_kernel() {
    const int CH = (NN + 1023) / 1024;
    __shared__ int ssum[1024];
    int t = threadIdx.x;
    int c0 = t*CH, c1 = min(c0+CH, NN);
    int s = 0;
    for (int i = c0; i < c1; ++i) s += g_cnt[i];
    ssum[t] = s;
    __syncthreads();
    for (int d = 1; d < 1024; d <<= 1) {
        int v = (t >= d) ? ssum[t-d] : 0;
        __syncthreads();
        ssum[t] += v;
        __syncthreads();
    }
    int run = (t == 0) ? 0 : ssum[t-1];
    for (int i = c0; i < c1; ++i) { g_off[i] = run; g_cur[i] = run; run += g_cnt[i]; }
    if (t == 0) g_off[NN] = ssum[1023];
}
__global__ void fill_kernel(const int* __restrict__ ei) {
    int e = blockIdx.x*blockDim.x + threadIdx.x;
    if (e >= EE) return;
    int d = ei[EE + e];
    int p = atomicAdd(&g_cur[d], 1);
    g_csr_src[p] = ei[e];
    g_csr_eid[p] = e;
}
__global__ void deg_kernel(const float* __restrict__ ew) {
    int gw = (blockIdx.x*blockDim.x + threadIdx.x) >> 5;
    int lane = threadIdx.x & 31;
    if (gw >= NN) return;
    int b0 = g_off[gw], b1 = g_off[gw+1];
    float s = 0.f;
    for (int j = b0 + lane; j < b1; j += 32) s += ew[g_csr_eid[j]];
    #pragma unroll
    for (int o = 16; o; o >>= 1) s += __shfl_down_sync(0xffffffffu, s, o);
    if (lane == 0) g_dis[gw] = rsqrtf(1.f + s);
}

// ---------------- weight prep (fp32, transposed [NPAD][K]) ----------------
__global__ void prep_Wgcn_kernel(const float* __restrict__ W) {
    int i = blockIdx.x*blockDim.x + threadIdx.x;
    if (i >= NPAD*FIN) return;
    int n = i / FIN, k = i % FIN;
    g_wgcn[i] = (n < HID) ? W[k*HID + n] : 0.f;
}
__global__ void prep_Wstack2_kernel(const float* __restrict__ W1, const float* __restrict__ W2) {
    int i = blockIdx.x*blockDim.x + threadIdx.x;
    if (i >= 2*NPAD*HH) return;
    const float* W = (i < NPAD*HH) ? W1 : W2;
    float* out = (i < NPAD*HH) ? g_ws1 : g_ws2;
    int j = (i < NPAD*HH) ? i : i - NPAD*HH;
    int n = j / HH, k = j % HH;
    float v = 0.f;
    if (n < HID) {
        int h = k / HID, kk = k % HID;
        v = 0.25f * W[kk*HH + h*HID + n];
    }
    out[j] = v;
}
__global__ void prep_Wfc_kernel(const float* __restrict__ W1, const float* __restrict__ W2) {
    int i = blockIdx.x*blockDim.x + threadIdx.x;
    if (i >= NPAD*264) return;
    int n = i / 264, k = i % 264;
    float v = 0.f;
    if (n < HID) v = (k < HID) ? W1[k*HID + n] : W2[(k-HID)*HID + n];
    g_wfc[i] = v;
}
__global__ void prep_esd_bias_kernel(const float* __restrict__ W1,
                                     const float* __restrict__ as1, const float* __restrict__ ad1,
                                     const float* __restrict__ W2,
                                     const float* __restrict__ as2, const float* __restrict__ ad2,
                                     const float* __restrict__ b1, const float* __restrict__ b2,
                                     const float* __restrict__ pro) {
    int i = blockIdx.x*blockDim.x + threadIdx.x;
    if (i < 2*HID*8) {
        const float* W = (i < HID*8) ? W1 : W2;
        const float* as = (i < HID*8) ? as1 : as2;
        const float* ad = (i < HID*8) ? ad1 : ad2;
        float* out = (i < HID*8) ? g_wesd1 : g_wesd2;
        int j = (i < HID*8) ? i : i - HID*8;
        int k = j >> 3, q = j & 7, h = q >> 1;
        const float* a = (q & 1) ? ad : as;
        float s = 0.f;
        for (int c = 0; c < HID; ++c) s += W[k*HH + h*HID + c] * a[h*HID + c];
        out[j] = s;
    } else if (i < 2*HID*8 + HID) {
        int c = i - 2*HID*8;
        g_bias_fc[c] = b1[c] + b2[c] + pro[c];
    }
}

// ---------------- per-node scores ----------------
__global__ __launch_bounds__(256) void esd_kernel(const float* __restrict__ xin,
                                                  const float* __restrict__ wesd) {
    int gw = (blockIdx.x*blockDim.x + threadIdx.x) >> 5;
    int lane = threadIdx.x & 31;
    if (gw >= NN) return;
    const float* row = xin + gw*HID;
    float p[8] = {0,0,0,0,0,0,0,0};
    for (int c = lane; c < HID; c += 32) {
        float xv = row[c];
        const float* wr = wesd + c*8;
        #pragma unroll
        for (int q = 0; q < 8; ++q) p[q] += xv * wr[q];
    }
    #pragma unroll
    for (int q = 0; q < 8; ++q)
        #pragma unroll
        for (int o = 16; o; o >>= 1) p[q] += __shfl_down_sync(0xffffffffu, p[q], o);
    if (lane == 0) {
        ((float4*)g_es)[gw] = make_float4(p[0], p[2], p[4], p[6]);
        ((float4*)g_ed)[gw] = make_float4(p[1], p[3], p[5], p[7]);
    }
}

__device__ __forceinline__ float lrelu02(float v) { return v > 0.f ? v : 0.2f*v; }

// ---------------- GCN aggregation ----------------
__global__ void gcn_agg_kernel(const float* __restrict__ ew, const float* __restrict__ bias) {
    int n = blockIdx.x, c = threadIdx.x;   // blockDim 132
    float dn = g_dis[n];
    float acc = bias[c] + dn*dn*g_h0[n*HID + c];
    int b0 = g_off[n], b1 = g_off[n+1];
    for (int j = b0; j < b1; ++j) {
        int s = g_csr_src[j];
        int e = g_csr_eid[j];
        acc += g_dis[s] * ew[e] * dn * g_h0[s*HID + c];
    }
    g_x1[n*HID + c] = fmaxf(acc, 0.f);
}

// ---------------- GAT aggregate-first ----------------
__global__ __launch_bounds__(160) void gat_aggz_kernel(const float* __restrict__ xin) {
    __shared__ float4 sal[32];
    __shared__ int    ssrc[32];
    __shared__ float4 sinv_s;
    int n = blockIdx.x, tid = threadIdx.x, lane = tid & 31;
    int b0 = g_off[n], b1 = g_off[n+1];
    float4 edn = ((float4*)g_ed)[n];
    float4 en  = ((float4*)g_es)[n];
    if (tid < 32) {
        float4 ds = make_float4(0.f, 0.f, 0.f, 0.f);
        for (int j = b0 + lane; j < b1; j += 32) {
            int s = g_csr_src[j];
            float4 e4 = ((float4*)g_es)[s];
            ds.x += expf(lrelu02(e4.x + edn.x));
            ds.y += expf(lrelu02(e4.y + edn.y));
            ds.z += expf(lrelu02(e4.z + edn.z));
            ds.w += expf(lrelu02(e4.w + edn.w));
        }
        #pragma unroll
        for (int o = 16; o; o >>= 1) {
            ds.x += __shfl_down_sync(0xffffffffu, ds.x, o);
            ds.y += __shfl_down_sync(0xffffffffu, ds.y, o);
            ds.z += __shfl_down_sync(0xffffffffu, ds.z, o);
            ds.w += __shfl_down_sync(0xffffffffu, ds.w, o);
        }
        if (lane == 0) {
            float sx = expf(lrelu02(en.x + edn.x));
            float sy = expf(lrelu02(en.y + edn.y));
            float sz = expf(lrelu02(en.z + edn.z));
            float sw = expf(lrelu02(en.w + edn.w));
            sinv_s = make_float4(1.f/(ds.x+sx), 1.f/(ds.y+sy), 1.f/(ds.z+sz), 1.f/(ds.w+sw));
        }
    }
    __syncthreads();
    float4 inv = sinv_s;
    float a0 = expf(lrelu02(en.x + edn.x)) * inv.x;
    float a1 = expf(lrelu02(en.y + edn.y)) * inv.y;
    float a2 = expf(lrelu02(en.z + edn.z)) * inv.z;
    float a3 = expf(lrelu02(en.w + edn.w)) * inv.w;
    float xv0 = (tid < HID) ? xin[n*HID + tid] : 0.f;
    float acc0 = a0*xv0, acc1 = a1*xv0, acc2 = a2*xv0, acc3 = a3*xv0;
    for (int base = b0; base < b1; base += 32) {
        int cnt = min(32, b1 - base);
        if (tid < 32 && base + tid < b1) {
            int j = base + tid;
            int s = g_csr_src[j];
            float4 e4 = ((float4*)g_es)[s];
            float4 al;
            al.x = expf(lrelu02(e4.x + edn.x)) * inv.x;
            al.y = expf(lrelu02(e4.y + edn.y)) * inv.y;
            al.z = expf(lrelu02(e4.z + edn.z)) * inv.z;
            al.w = expf(lrelu02(e4.w + edn.w)) * inv.w;
            sal[tid] = al;
            ssrc[tid] = s;
        }
        __syncthreads();
        if (tid < HID) {
            for (int t = 0; t < cnt; ++t) {
                float xv = xin[ssrc[t]*HID + tid];
                float4 al = sal[t];
                acc0 += al.x*xv; acc1 += al.y*xv; acc2 += al.z*xv; acc3 += al.w*xv;
            }
        }
        __syncthreads();
    }
    if (tid < HID) {
        float* zp = g_Z + (size_t)n*HH;
        zp[tid]         = acc0;
        zp[HID + tid]   = acc1;
        zp[2*HID + tid] = acc2;
        zp[3*HID + tid] = acc3;
    }
}

// ---------------- tf32 GEMM, 128x144 block, cp.async double-buffered ----------------
#define SAS 36
#define SMA (128*SAS)            // floats
#define SMB (NPAD*SAS)           // floats
#define SMEM_GEMM_BYTES ((2*SMA + 2*SMB)*4)   // 78336

#define CP_A16(dst, src, sz) asm volatile("cp.async.ca.shared.global [%0], [%1], 16, %2;" :: "r"(dst), "l"(src), "r"(sz) : "memory")
#define CP_COMMIT() asm volatile("cp.async.commit_group;" ::: "memory")
#define CP_WAIT1()  asm volatile("cp.async.wait_group 1;" ::: "memory")
#define CP_WAIT0()  asm volatile("cp.async.wait_group 0;" ::: "memory")

__device__ __forceinline__ void mma_tf32(float* d, const uint32_t* a, const uint32_t* b) {
    asm volatile("mma.sync.aligned.m16n8k8.row.col.f32.tf32.tf32.f32 "
        "{%0,%1,%2,%3}, {%4,%5,%6,%7}, {%8,%9}, {%0,%1,%2,%3};"
        : "+f"(d[0]), "+f"(d[1]), "+f"(d[2]), "+f"(d[3])
        : "r"(a[0]), "r"(a[1]), "r"(a[2]), "r"(a[3]), "r"(b[0]), "r"(b[1]));
}
__device__ __forceinline__ unsigned fmap(float f) {
    unsigned u = __float_as_uint(f);
    return (u & 0x80000000u) ? ~u : (u | 0x80000000u);
}

template<bool ALIGN16>
__device__ __forceinline__ void load_tile(
    float* sA, float* sB, const float* A1, const float* A2, const float* B,
    int m0, int k0, int M, int K, int tid)
{
    if (ALIGN16) {
        #pragma unroll
        for (int i = 0; i < 4; ++i) {
            int c = tid + i*256;              // 128*8 = 1024 float4 slots
            int row = c >> 3, j = c & 7;
            int gm = m0 + row, gk = k0 + j*4;
            int sz = (gm < M && gk < K) ? 16 : 0;
            const float* src = A1;
            if (sz) {
                if (A2) src = (gk < HID) ? A1 + (size_t)gm*HID + gk
                                         : A2 + (size_t)gm*HID + (gk - HID);
                else    src = A1 + (size_t)gm*K + gk;
            }
            uint32_t dst = (uint32_t)__cvta_generic_to_shared(sA + row*SAS + j*4);
            CP_A16(dst, src, sz);
        }
        #pragma unroll
        for (int i = 0; i < 5; ++i) {
            int c = tid + i*256;              // 144*8 = 1152 float4 slots
            if (c >= NPAD*8) break;
            int row = c >> 3, j = c & 7;
            int gk = k0 + j*4;
            int sz = (gk < K) ? 16 : 0;
            const float* src = sz ? B + (size_t)row*K + gk : B;
            uint32_t dst = (uint32_t)__cvta_generic_to_shared(sB + row*SAS + j*4);
            CP_A16(dst, src, sz);
        }
    } else {
        #pragma unroll
        for (int i = 0; i < 4; ++i) {
            int c = tid + i*256;
            int row = c >> 3, j = c & 7;
            int gm = m0 + row;
            #pragma unroll
            for (int q = 0; q < 4; ++q) {
                int gk = k0 + j*4 + q;
                sA[row*SAS + j*4 + q] = (gm < M && gk < K) ? A1[(size_t)gm*K + gk] : 0.f;
            }
        }
        #pragma unroll
        for (int i = 0; i < 5; ++i) {
            int c = tid + i*256;
            if (c >= NPAD*8) break;
            int row = c >> 3, j = c & 7;
            #pragma unroll
            for (int q = 0; q < 4; ++q) {
                int gk = k0 + j*4 + q;
                sB[row*SAS + j*4 + q] = (gk < K) ? B[(size_t)row*K + gk] : 0.f;
            }
        }
    }
}

// 8 warps: warpM = wid&3 (32 rows), warpN = wid>>2 (72 cols, nt=9)
template<int EPI, bool TRI, bool ALIGN16>
__global__ __launch_bounds__(256, 2) void tf32_gemm_kernel(
    const float* __restrict__ A1, const float* __restrict__ A2,
    const float* __restrict__ B, const float* __restrict__ bias,
    float* __restrict__ C, const int* __restrict__ batch,
    int M, int Nreal, int K)
{
    extern __shared__ float smem[];
    float* sAbuf[2] = { smem, smem + SMA };
    float* sBbuf[2] = { smem + 2*SMA, smem + 2*SMA + SMB };

    int tid = threadIdx.x, lane = tid & 31, wid = tid >> 5;
    int warpM = wid & 3, warpN = wid >> 2;
    int m0 = blockIdx.x*128;

    float acc[2][9][4];
    #pragma unroll
    for (int i = 0; i < 2; ++i)
        #pragma unroll
        for (int j = 0; j < 9; ++j)
            #pragma unroll
            for (int q = 0; q < 4; ++q) acc[i][j][q] = 0.f;

    int kt = (K + 31) >> 5;
    load_tile<ALIGN16>(sAbuf[0], sBbuf[0], A1, A2, B, m0, 0, M, K, tid);
    if (ALIGN16) CP_COMMIT();

    for (int t = 0; t < kt; ++t) {
        int s = t & 1;
        if (t + 1 < kt) {
            load_tile<ALIGN16>(sAbuf[s^1], sBbuf[s^1], A1, A2, B, m0, (t+1)*32, M, K, tid);
            if (ALIGN16) CP_COMMIT();
        }
        if (ALIGN16) { if (t + 1 < kt) CP_WAIT1(); else CP_WAIT0(); }
        __syncthreads();

        const float* cA = sAbuf[s];
        const float* cB = sBbuf[s];
        int gr = lane >> 2, gc = lane & 3;
        #pragma unroll
        for (int kk = 0; kk < 4; ++kk) {
            int c0 = kk*8 + gc;
            uint32_t ah[2][4], al[2][4];
            #pragma unroll
            for (int mt = 0; mt < 2; ++mt) {
                int r0 = warpM*32 + mt*16 + gr;
                float av[4];
                av[0] = cA[r0*SAS + c0];
                av[1] = cA[(r0+8)*SAS + c0];
                av[2] = cA[r0*SAS + c0 + 4];
                av[3] = cA[(r0+8)*SAS + c0 + 4];
                #pragma unroll
                for (int q = 0; q < 4; ++q) {
                    if (TRI) {
                        uint32_t h = __float_as_uint(av[q]) & 0xFFFFE000u;
                        ah[mt][q] = h;
                        al[mt][q] = __float_as_uint(av[q] - __uint_as_float(h));
                    } else {
                        ah[mt][q] = __float_as_uint(av[q]);
                    }
                }
            }
            #pragma unroll
            for (int nt = 0; nt < 9; ++nt) {
                int n = warpN*72 + nt*8 + gr;
                float bv[2];
                bv[0] = cB[n*SAS + c0];
                bv[1] = cB[n*SAS + c0 + 4];
                uint32_t bh[2], bl[2];
                #pragma unroll
                for (int q = 0; q < 2; ++q) {
                    if (TRI) {
                        uint32_t h = __float_as_uint(bv[q]) & 0xFFFFE000u;
                        bh[q] = h;
                        bl[q] = __float_as_uint(bv[q] - __uint_as_float(h));
                    } else {
                        bh[q] = __float_as_uint(bv[q]);
                    }
                }
                #pragma unroll
                for (int mt = 0; mt < 2; ++mt) {
                    mma_tf32(acc[mt][nt], ah[mt], bh);
                    if (TRI) {
                        mma_tf32(acc[mt][nt], ah[mt], bl);
                        mma_tf32(acc[mt][nt], al[mt], bh);
                    }
                }
            }
        }
        __syncthreads();
    }

    // ---- epilogue ----
    int gr = lane >> 2, gc2 = 2*(lane & 3);
    #pragma unroll
    for (int mt = 0; mt < 2; ++mt) {
        #pragma unroll
        for (int nt = 0; nt < 9; ++nt) {
            int n = warpN*72 + nt*8 + gc2;
            if (n >= Nreal) continue;
            float bx = bias ? bias[n] : 0.f;
            float by = bias ? bias[n+1] : 0.f;
            #pragma unroll
            for (int rr = 0; rr < 2; ++rr) {
                int m = m0 + warpM*32 + mt*16 + gr + rr*8;
                if (m >= M) continue;
                float v0 = acc[mt][nt][rr*2+0] + bx;
                float v1 = acc[mt][nt][rr*2+1] + by;
                if (EPI == 0) {
                    *(float2*)(C + (size_t)m*Nreal + n) = make_float2(v0, v1);
                } else if (EPI == 1) {
                    *(float2*)(C + (size_t)m*Nreal + n) = make_float2(fmaxf(v0, 0.f), fmaxf(v1, 0.f));
                } else {
                    float2 xc2 = *(const float2*)(A1 + (size_t)m*HID + n);
                    float2 xp2 = *(const float2*)(A2 + (size_t)m*HID + n);
                    float z0 = 1.f / (1.f + expf(-v0));
                    float z1 = 1.f / (1.f + expf(-v1));
                    float o0 = z0*xc2.x + (1.f - z0)*xp2.x;
                    float o1 = z1*xc2.y + (1.f - z1)*xp2.y;
                    if (EPI == 2) {
                        *(float2*)(C + (size_t)m*Nreal + n) = make_float2(o0, o1);
                    } else {
                        int bi = batch[m];
                        atomicMax(&g_pool_u[bi*HID + n],     fmap(o0));
                        atomicMax(&g_pool_u[bi*HID + n + 1], fmap(o1));
                    }
                }
            }
        }
    }
}

// ---------------- small SIMT GEMM (head) ----------------
template<bool RELU>
__global__ __launch_bounds__(256) void gemm_kernel(
    const float* __restrict__ A, const float* __restrict__ B,
    const float* __restrict__ bias, float* __restrict__ C,
    int M, int N, int K)
{
    const int BM = 64, BN = 64, BK = 16;
    __shared__ float As[BK][BM+4];
    __shared__ float Bs[BK][BN];
    int n0 = blockIdx.x*BN, m0 = blockIdx.y*BM;
    int tid = threadIdx.x;
    int tx = tid & 15, ty = tid >> 4;
    float acc[4][4] = {};
    for (int k0 = 0; k0 < K; k0 += BK) {
        #pragma unroll
        for (int r = 0; r < 4; ++r) {
            int idx = tid + r*256;
            int i = idx >> 4, j = idx & 15;
            int gm = m0 + i, gk = k0 + j;
            As[j][i] = (gm < M && gk < K) ? A[gm*K + gk] : 0.f;
        }
        #pragma unroll
        for (int r = 0; r < 4; ++r) {
            int idx = tid + r*256;
            int j = idx >> 6, i = idx & 63;
            int gk = k0 + j, gn = n0 + i;
            Bs[j][i] = (gk < K && gn < N) ? B[gk*N + gn] : 0.f;
        }
        __syncthreads();
        #pragma unroll
        for (int k = 0; k < BK; ++k) {
            float a[4], b[4];
            #pragma unroll
            for (int i = 0; i < 4; ++i) a[i] = As[k][ty*4+i];
            #pragma unroll
            for (int j = 0; j < 4; ++j) b[j] = Bs[k][tx*4+j];
            #pragma unroll
            for (int i = 0; i < 4; ++i)
                #pragma unroll
                for (int j = 0; j < 4; ++j)
                    acc[i][j] += a[i]*b[j];
        }
        __syncthreads();
    }
    #pragma unroll
    for (int i = 0; i < 4; ++i) {
        int gm = m0 + ty*4 + i;
        if (gm >= M) continue;
        #pragma unroll
        for (int j = 0; j < 4; ++j) {
            int gn = n0 + tx*4 + j;
            if (gn >= N) continue;
            float v = acc[i][j] + (bias ? bias[gn] : 0.f);
            if (RELU) v = fmaxf(v, 0.f);
            C[gm*N + gn] = v;
        }
    }
}

// ---------------- pool decode ----------------
__global__ void pool_decode_kernel() {
    int i = blockIdx.x*blockDim.x + threadIdx.x;
    if (i >= GG*HID) return;
    unsigned u = g_pool_u[i];
    g_pool[i] = (u & 0x80000000u) ? __uint_as_float(u ^ 0x80000000u)
                                  : __uint_as_float(~u);
}

// ---------------- launch ----------------
extern "C" void kernel_launch(void* const* d_in, const int* in_sizes, int n_in,
                              void* d_out, int out_size) {
    const float* x        = (const float*)d_in[0];
    const int*   ei       = (const int*)  d_in[1];
    const float* ew       = (const float*)d_in[2];
    const int*   batch    = (const int*)  d_in[3];
    const float* W_gcn    = (const float*)d_in[4];
    const float* b_gcn    = (const float*)d_in[5];
    const float* W_gat1   = (const float*)d_in[6];
    const float* a_src1   = (const float*)d_in[7];
    const float* a_dst1   = (const float*)d_in[8];
    const float* b_gat1   = (const float*)d_in[9];
    const float* W_gat2   = (const float*)d_in[10];
    const float* a_src2   = (const float*)d_in[11];
    const float* a_dst2   = (const float*)d_in[12];
    const float* b_gat2   = (const float*)d_in[13];
    const float* W_fc1    = (const float*)d_in[14];
    const float* b_fc1    = (const float*)d_in[15];
    const float* W_fc2    = (const float*)d_in[16];
    const float* b_fc2    = (const float*)d_in[17];
    const float* pro_bias = (const float*)d_in[18];
    const float* W_g1     = (const float*)d_in[19];
    const float* b_g1     = (const float*)d_in[20];
    const float* W_g2     = (const float*)d_in[21];
    const float* b_g2     = (const float*)d_in[22];
    float* out = (float*)d_out;

    float *p_h0, *p_x1, *p_x2, *p_Z, *p_xc, *p_pool, *p_hid, *p_bias_fc, *p_wesd1, *p_wesd2;
    float *p_wgcn, *p_ws1, *p_ws2, *p_wfc;
    cudaGetSymbolAddress((void**)&p_h0,   g_h0);
    cudaGetSymbolAddress((void**)&p_x1,   g_x1);
    cudaGetSymbolAddress((void**)&p_x2,   g_x2);
    cudaGetSymbolAddress((void**)&p_Z,    g_Z);
    cudaGetSymbolAddress((void**)&p_xc,   g_xc);
    cudaGetSymbolAddress((void**)&p_pool, g_pool);
    cudaGetSymbolAddress((void**)&p_hid,  g_hid);
    cudaGetSymbolAddress((void**)&p_bias_fc, g_bias_fc);
    cudaGetSymbolAddress((void**)&p_wesd1, g_wesd1);
    cudaGetSymbolAddress((void**)&p_wesd2, g_wesd2);
    cudaGetSymbolAddress((void**)&p_wgcn, g_wgcn);
    cudaGetSymbolAddress((void**)&p_ws1,  g_ws1);
    cudaGetSymbolAddress((void**)&p_ws2,  g_ws2);
    cudaGetSymbolAddress((void**)&p_wfc,  g_wfc);

    static bool attr_done = false;
    if (!attr_done) {
        cudaFuncSetAttribute(tf32_gemm_kernel<0,true ,false>, cudaFuncAttributeMaxDynamicSharedMemorySize, SMEM_GEMM_BYTES);
        cudaFuncSetAttribute(tf32_gemm_kernel<1,true ,true >, cudaFuncAttributeMaxDynamicSharedMemorySize, SMEM_GEMM_BYTES);
        cudaFuncSetAttribute(tf32_gemm_kernel<0,true ,true >, cudaFuncAttributeMaxDynamicSharedMemorySize, SMEM_GEMM_BYTES);
        cudaFuncSetAttribute(tf32_gemm_kernel<2,false,true >, cudaFuncAttributeMaxDynamicSharedMemorySize, SMEM_GEMM_BYTES);
        cudaFuncSetAttribute(tf32_gemm_kernel<3,false,true >, cudaFuncAttributeMaxDynamicSharedMemorySize, SMEM_GEMM_BYTES);
        attr_done = true;
    }

    const int TB = 256;
    const int MT = (NN + 127)/128;   // 235
    dim3 ggrid(MT, 1);               // single block-column covers all 144 padded cols

    // slots 1-3: independent prep; slot 4 = GCN GEMM (profiled)
    prep_Wgcn_kernel<<<(NPAD*FIN+TB-1)/TB, TB>>>(W_gcn);
    zero_cnt_pool_kernel<<<(NN+TB-1)/TB, TB>>>();
    hist_kernel<<<(EE+TB-1)/TB, TB>>>(ei);
    // slot 4: GCN transform GEMM (K=33, sync path, TRI)
    tf32_gemm_kernel<0,true,false><<<ggrid, 256, SMEM_GEMM_BYTES>>>(x, nullptr, p_wgcn, nullptr, p_h0, nullptr, NN, HID, FIN);
    // CSR chain
    scan_kernel<<<1, 1024>>>();
    fill_kernel<<<(EE+TB-1)/TB, TB>>>(ei);
    deg_kernel<<<(NN*32+TB-1)/TB, TB>>>(ew);
    // weight prep (merged)
    prep_Wstack2_kernel<<<(2*NPAD*HH+TB-1)/TB, TB>>>(W_gat1, W_gat2);
    prep_Wfc_kernel<<<(NPAD*264+TB-1)/TB, TB>>>(W_fc1, W_fc2);
    prep_esd_bias_kernel<<<(2*HID*8+HID+TB-1)/TB, TB>>>(W_gat1, a_src1, a_dst1,
                                                        W_gat2, a_src2, a_dst2,
                                                        b_fc1, b_fc2, pro_bias);

    // layer 0
    gcn_agg_kernel<<<NN, HID>>>(ew, b_gcn);

    // layer 1: GAT + relu + gated fusion
    esd_kernel<<<(NN*32+TB-1)/TB, TB>>>(p_x1, p_wesd1);
    gat_aggz_kernel<<<NN, 160>>>(p_x1);
    tf32_gemm_kernel<1,true ,true><<<ggrid, 256, SMEM_GEMM_BYTES>>>(p_Z, nullptr, p_ws1, b_gat1, p_xc, nullptr, NN, HID, HH);
    tf32_gemm_kernel<2,false,true><<<ggrid, 256, SMEM_GEMM_BYTES>>>(p_xc, p_x1, p_wfc, p_bias_fc, p_x2, nullptr, NN, HID, 264);

    // layer 2: GAT + gated fusion + fused pool
    esd_kernel<<<(NN*32+TB-1)/TB, TB>>>(p_x2, p_wesd2);
    gat_aggz_kernel<<<NN, 160>>>(p_x2);
    tf32_gemm_kernel<0,true ,true><<<ggrid, 256, SMEM_GEMM_BYTES>>>(p_Z, nullptr, p_ws2, b_gat2, p_xc, nullptr, NN, HID, HH);
    tf32_gemm_kernel<3,false,true><<<ggrid, 256, SMEM_GEMM_BYTES>>>(p_xc, p_x2, p_wfc, p_bias_fc, nullptr, batch, NN, HID, 264);

    // pool decode + head
    pool_decode_kernel<<<(GG*HID+TB-1)/TB, TB>>>();
    gemm_kernel<true ><<<dim3(GFC/64, 1), 256>>>(p_pool, W_g1, b_g1, p_hid, GG, GFC, HID);
    gemm_kernel<false><<<dim3(OUTD/64, 1), 256>>>(p_hid, W_g2, b_g2, out, GG, OUTD, GFC);
}

// round 10
// speedup vs baseline: 1.1001x; 1.1001x over previous
#include <cuda_runtime.h>
#include <math.h>
#include <stdint.h>

// ---------------- problem constants ----------------
#define NN    30000
#define EE    300000
#define FIN   33
#define HID   132
#define HEADS 4
#define HH    528
#define GG    64
#define GFC   1024
#define OUTD  128
#define NPAD  144

// ---------------- scratch (device globals) ----------------
__device__ __align__(16) float g_dis[NN];
__device__ int   g_cnt[NN];
__device__ int   g_off[NN+1];
__device__ int   g_cur[NN];
__device__ int   g_csr_src[EE];
__device__ int   g_csr_eid[EE];
__device__ __align__(16) float g_h0[NN*HID];
__device__ __align__(16) float g_x1[NN*HID];
__device__ __align__(16) float g_x2[NN*HID];
__device__ __align__(16) float g_Z[NN*HH];
__device__ __align__(16) float g_es[NN*HEADS];
__device__ __align__(16) float g_ed[NN*HEADS];
__device__ unsigned g_pool_u[GG*HID];
__device__ __align__(16) float g_hid[GG*GFC];
__device__ __align__(16) float g_wesd1[HID*8];
__device__ __align__(16) float g_wesd2[HID*8];
// fp32 prepped weights
__device__ __align__(16) float g_wgcn[NPAD*FIN];
__device__ __align__(16) float g_ws1[NPAD*HH];
__device__ __align__(16) float g_ws2[NPAD*HH];
__device__ __align__(16) float g_wfc1[NPAD*HID];
__device__ __align__(16) float g_wfc2[NPAD*HID];
__device__ float g_bias_fc[HID];

// ---------------- CSR build ----------------
__global__ void zero_cnt_pool_kernel() {
    int i = blockIdx.x*blockDim.x + threadIdx.x;
    if (i < NN) g_cnt[i] = 0;
    if (i < GG*HID) g_pool_u[i] = 0u;
}
__global__ void hist_kernel(const int* __restrict__ ei) {
    int e = blockIdx.x*blockDim.x + threadIdx.x;
    if (e < EE) atomicAdd(&g_cnt[ei[EE + e]], 1);
}
__global__ void scan_kernel() {
    const int CH = (NN + 1023) / 1024;
    __shared__ int ssum[1024];
    int t = threadIdx.x;
    int c0 = t*CH, c1 = min(c0+CH, NN);
    int s = 0;
    for (int i = c0; i < c1; ++i) s += g_cnt[i];
    ssum[t] = s;
    __syncthreads();
    for (int d = 1; d < 1024; d <<= 1) {
        int v = (t >= d) ? ssum[t-d] : 0;
        __syncthreads();
        ssum[t] += v;
        __syncthreads();
    }
    int run = (t == 0) ? 0 : ssum[t-1];
    for (int i = c0; i < c1; ++i) { g_off[i] = run; g_cur[i] = run; run += g_cnt[i]; }
    if (t == 0) g_off[NN] = ssum[1023];
}
__global__ void fill_kernel(const int* __restrict__ ei) {
    int e = blockIdx.x*blockDim.x + threadIdx.x;
    if (e >= EE) return;
    int d = ei[EE + e];
    int p = atomicAdd(&g_cur[d], 1);
    g_csr_src[p] = ei[e];
    g_csr_eid[p] = e;
}
__global__ void deg_kernel(const float* __restrict__ ew) {
    int gw = (blockIdx.x*blockDim.x + threadIdx.x) >> 5;
    int lane = threadIdx.x & 31;
    if (gw >= NN) return;
    int b0 = g_off[gw], b1 = g_off[gw+1];
    float s = 0.f;
    for (int j = b0 + lane; j < b1; j += 32) s += ew[g_csr_eid[j]];
    #pragma unroll
    for (int o = 16; o; o >>= 1) s += __shfl_down_sync(0xffffffffu, s, o);
    if (lane == 0) g_dis[gw] = rsqrtf(1.f + s);
}

// ---------------- weight prep ----------------
__global__ void prep_Wgcn_kernel(const float* __restrict__ W) {
    int i = blockIdx.x*blockDim.x + threadIdx.x;
    if (i >= NPAD*FIN) return;
    int n = i / FIN, k = i % FIN;
    g_wgcn[i] = (n < HID) ? W[k*HID + n] : 0.f;
}
__global__ void prep_Wstack2_kernel(const float* __restrict__ W1, const float* __restrict__ W2) {
    int i = blockIdx.x*blockDim.x + threadIdx.x;
    if (i >= 2*NPAD*HH) return;
    const float* W = (i < NPAD*HH) ? W1 : W2;
    float* out = (i < NPAD*HH) ? g_ws1 : g_ws2;
    int j = (i < NPAD*HH) ? i : i - NPAD*HH;
    int n = j / HH, k = j % HH;
    float v = 0.f;
    if (n < HID) {
        int h = k / HID, kk = k % HID;
        v = 0.25f * W[kk*HH + h*HID + n];
    }
    out[j] = v;
}
// gate weights split: g_wfc1[144][132] from W_fc1, g_wfc2[144][132] from W_fc2
__global__ void prep_Wfc12_kernel(const float* __restrict__ W1, const float* __restrict__ W2) {
    int i = blockIdx.x*blockDim.x + threadIdx.x;
    if (i >= 2*NPAD*HID) return;
    const float* W = (i < NPAD*HID) ? W1 : W2;
    float* out = (i < NPAD*HID) ? g_wfc1 : g_wfc2;
    int j = (i < NPAD*HID) ? i : i - NPAD*HID;
    int n = j / HID, k = j % HID;
    out[j] = (n < HID) ? W[k*HID + n] : 0.f;
}
__global__ void prep_esd_bias_kernel(const float* __restrict__ W1,
                                     const float* __restrict__ as1, const float* __restrict__ ad1,
                                     const float* __restrict__ W2,
                                     const float* __restrict__ as2, const float* __restrict__ ad2,
                                     const float* __restrict__ b1, const float* __restrict__ b2,
                                     const float* __restrict__ pro) {
    int i = blockIdx.x*blockDim.x + threadIdx.x;
    if (i < 2*HID*8) {
        const float* W = (i < HID*8) ? W1 : W2;
        const float* as = (i < HID*8) ? as1 : as2;
        const float* ad = (i < HID*8) ? ad1 : ad2;
        float* out = (i < HID*8) ? g_wesd1 : g_wesd2;
        int j = (i < HID*8) ? i : i - HID*8;
        int k = j >> 3, q = j & 7, h = q >> 1;
        const float* a = (q & 1) ? ad : as;
        float s = 0.f;
        for (int c = 0; c < HID; ++c) s += W[k*HH + h*HID + c] * a[h*HID + c];
        out[j] = s;
    } else if (i < 2*HID*8 + HID) {
        int c = i - 2*HID*8;
        g_bias_fc[c] = b1[c] + b2[c] + pro[c];
    }
}

// ---------------- per-node scores ----------------
__global__ __launch_bounds__(256) void esd_kernel(const float* __restrict__ xin,
                                                  const float* __restrict__ wesd) {
    int gw = (blockIdx.x*blockDim.x + threadIdx.x) >> 5;
    int lane = threadIdx.x & 31;
    if (gw >= NN) return;
    const float* row = xin + gw*HID;
    float p[8] = {0,0,0,0,0,0,0,0};
    for (int c = lane; c < HID; c += 32) {
        float xv = row[c];
        const float* wr = wesd + c*8;
        #pragma unroll
        for (int q = 0; q < 8; ++q) p[q] += xv * wr[q];
    }
    #pragma unroll
    for (int q = 0; q < 8; ++q)
        #pragma unroll
        for (int o = 16; o; o >>= 1) p[q] += __shfl_down_sync(0xffffffffu, p[q], o);
    if (lane == 0) {
        ((float4*)g_es)[gw] = make_float4(p[0], p[2], p[4], p[6]);
        ((float4*)g_ed)[gw] = make_float4(p[1], p[3], p[5], p[7]);
    }
}

__device__ __forceinline__ float lrelu02(float v) { return v > 0.f ? v : 0.2f*v; }

// ---------------- GCN aggregation ----------------
__global__ void gcn_agg_kernel(const float* __restrict__ ew, const float* __restrict__ bias) {
    int n = blockIdx.x, c = threadIdx.x;
    float dn = g_dis[n];
    float acc = bias[c] + dn*dn*g_h0[n*HID + c];
    int b0 = g_off[n], b1 = g_off[n+1];
    for (int j = b0; j < b1; ++j) {
        int s = g_csr_src[j];
        int e = g_csr_eid[j];
        acc += g_dis[s] * ew[e] * dn * g_h0[s*HID + c];
    }
    g_x1[n*HID + c] = fmaxf(acc, 0.f);
}

// ---------------- GAT aggregate-first ----------------
__global__ __launch_bounds__(160) void gat_aggz_kernel(const float* __restrict__ xin) {
    __shared__ float4 sal[32];
    __shared__ int    ssrc[32];
    __shared__ float4 sinv_s;
    int n = blockIdx.x, tid = threadIdx.x, lane = tid & 31;
    int b0 = g_off[n], b1 = g_off[n+1];
    float4 edn = ((float4*)g_ed)[n];
    float4 en  = ((float4*)g_es)[n];
    if (tid < 32) {
        float4 ds = make_float4(0.f, 0.f, 0.f, 0.f);
        for (int j = b0 + lane; j < b1; j += 32) {
            int s = g_csr_src[j];
            float4 e4 = ((float4*)g_es)[s];
            ds.x += expf(lrelu02(e4.x + edn.x));
            ds.y += expf(lrelu02(e4.y + edn.y));
            ds.z += expf(lrelu02(e4.z + edn.z));
            ds.w += expf(lrelu02(e4.w + edn.w));
        }
        #pragma unroll
        for (int o = 16; o; o >>= 1) {
            ds.x += __shfl_down_sync(0xffffffffu, ds.x, o);
            ds.y += __shfl_down_sync(0xffffffffu, ds.y, o);
            ds.z += __shfl_down_sync(0xffffffffu, ds.z, o);
            ds.w += __shfl_down_sync(0xffffffffu, ds.w, o);
        }
        if (lane == 0) {
            float sx = expf(lrelu02(en.x + edn.x));
            float sy = expf(lrelu02(en.y + edn.y));
            float sz = expf(lrelu02(en.z + edn.z));
            float sw = expf(lrelu02(en.w + edn.w));
            sinv_s = make_float4(1.f/(ds.x+sx), 1.f/(ds.y+sy), 1.f/(ds.z+sz), 1.f/(ds.w+sw));
        }
    }
    __syncthreads();
    float4 inv = sinv_s;
    float a0 = expf(lrelu02(en.x + edn.x)) * inv.x;
    float a1 = expf(lrelu02(en.y + edn.y)) * inv.y;
    float a2 = expf(lrelu02(en.z + edn.z)) * inv.z;
    float a3 = expf(lrelu02(en.w + edn.w)) * inv.w;
    float xv0 = (tid < HID) ? xin[n*HID + tid] : 0.f;
    float acc0 = a0*xv0, acc1 = a1*xv0, acc2 = a2*xv0, acc3 = a3*xv0;
    for (int base = b0; base < b1; base += 32) {
        int cnt = min(32, b1 - base);
        if (tid < 32 && base + tid < b1) {
            int j = base + tid;
            int s = g_csr_src[j];
            float4 e4 = ((float4*)g_es)[s];
            float4 al;
            al.x = expf(lrelu02(e4.x + edn.x)) * inv.x;
            al.y = expf(lrelu02(e4.y + edn.y)) * inv.y;
            al.z = expf(lrelu02(e4.z + edn.z)) * inv.z;
            al.w = expf(lrelu02(e4.w + edn.w)) * inv.w;
            sal[tid] = al;
            ssrc[tid] = s;
        }
        __syncthreads();
        if (tid < HID) {
            for (int t = 0; t < cnt; ++t) {
                float xv = xin[ssrc[t]*HID + tid];
                float4 al = sal[t];
                acc0 += al.x*xv; acc1 += al.y*xv; acc2 += al.z*xv; acc3 += al.w*xv;
            }
        }
        __syncthreads();
    }
    if (tid < HID) {
        float* zp = g_Z + (size_t)n*HH;
        zp[tid]         = acc0;
        zp[HID + tid]   = acc1;
        zp[2*HID + tid] = acc2;
        zp[3*HID + tid] = acc3;
    }
}

// ---------------- GEMM common ----------------
#define SAS 36
#define SMA (128*SAS)            // floats
#define SMB (NPAD*SAS)           // floats
#define SMEM_GEMM_BYTES ((2*SMA + 2*SMB)*4)   // 78336
// fused kernel: sxc (128*132 fl) + s2A (128*36) + s2B (144*36)
#define SXC_FLOATS (128*HID)
#define SMEM_FUSED_BYTES ((SXC_FLOATS + SMA + SMB)*4)   // 106752

#define CP_A16(dst, src, sz) asm volatile("cp.async.ca.shared.global [%0], [%1], 16, %2;" :: "r"(dst), "l"(src), "r"(sz) : "memory")
#define CP_COMMIT() asm volatile("cp.async.commit_group;" ::: "memory")
#define CP_WAIT1()  asm volatile("cp.async.wait_group 1;" ::: "memory")
#define CP_WAIT0()  asm volatile("cp.async.wait_group 0;" ::: "memory")

__device__ __forceinline__ void mma_tf32(float* d, const uint32_t* a, const uint32_t* b) {
    asm volatile("mma.sync.aligned.m16n8k8.row.col.f32.tf32.tf32.f32 "
        "{%0,%1,%2,%3}, {%4,%5,%6,%7}, {%8,%9}, {%0,%1,%2,%3};"
        : "+f"(d[0]), "+f"(d[1]), "+f"(d[2]), "+f"(d[3])
        : "r"(a[0]), "r"(a[1]), "r"(a[2]), "r"(a[3]), "r"(b[0]), "r"(b[1]));
}
__device__ __forceinline__ unsigned fmap(float f) {
    unsigned u = __float_as_uint(f);
    return (u & 0x80000000u) ? ~u : (u | 0x80000000u);
}
__device__ __forceinline__ float fmap_inv(unsigned u) {
    return (u & 0x80000000u) ? __uint_as_float(u ^ 0x80000000u) : __uint_as_float(~u);
}

template<bool ALIGN16>
__device__ __forceinline__ void load_tile(
    float* sA, float* sB, const float* A1, const float* B,
    int m0, int k0, int M, int K, int tid)
{
    if (ALIGN16) {
        #pragma unroll
        for (int i = 0; i < 4; ++i) {
            int c = tid + i*256;
            int row = c >> 3, j = c & 7;
            int gm = m0 + row, gk = k0 + j*4;
            int sz = (gm < M && gk < K) ? 16 : 0;
            const float* src = sz ? A1 + (size_t)gm*K + gk : A1;
            uint32_t dst = (uint32_t)__cvta_generic_to_shared(sA + row*SAS + j*4);
            CP_A16(dst, src, sz);
        }
        #pragma unroll
        for (int i = 0; i < 5; ++i) {
            int c = tid + i*256;
            if (c >= NPAD*8) break;
            int row = c >> 3, j = c & 7;
            int gk = k0 + j*4;
            int sz = (gk < K) ? 16 : 0;
            const float* src = sz ? B + (size_t)row*K + gk : B;
            uint32_t dst = (uint32_t)__cvta_generic_to_shared(sB + row*SAS + j*4);
            CP_A16(dst, src, sz);
        }
    } else {
        #pragma unroll
        for (int i = 0; i < 4; ++i) {
            int c = tid + i*256;
            int row = c >> 3, j = c & 7;
            int gm = m0 + row;
            #pragma unroll
            for (int q = 0; q < 4; ++q) {
                int gk = k0 + j*4 + q;
                sA[row*SAS + j*4 + q] = (gm < M && gk < K) ? A1[(size_t)gm*K + gk] : 0.f;
            }
        }
        #pragma unroll
        for (int i = 0; i < 5; ++i) {
            int c = tid + i*256;
            if (c >= NPAD*8) break;
            int row = c >> 3, j = c & 7;
            #pragma unroll
            for (int q = 0; q < 4; ++q) {
                int gk = k0 + j*4 + q;
                sB[row*SAS + j*4 + q] = (gk < K) ? B[(size_t)row*K + gk] : 0.f;
            }
        }
    }
}

// TRI main loop over K (shared by GCN kernel and fused phase 1); acc[2][9][4]
template<bool TRI, bool ALIGN16>
__device__ __forceinline__ void gemm_mainloop(
    float* smem, const float* A1, const float* B,
    int m0, int M, int K, int tid, int lane, int warpM, int warpN,
    float acc[2][9][4])
{
    float* sAbuf[2] = { smem, smem + SMA };
    float* sBbuf[2] = { smem + 2*SMA, smem + 2*SMA + SMB };
    int kt = (K + 31) >> 5;
    load_tile<ALIGN16>(sAbuf[0], sBbuf[0], A1, B, m0, 0, M, K, tid);
    if (ALIGN16) CP_COMMIT();
    for (int t = 0; t < kt; ++t) {
        int s = t & 1;
        if (t + 1 < kt) {
            load_tile<ALIGN16>(sAbuf[s^1], sBbuf[s^1], A1, B, m0, (t+1)*32, M, K, tid);
            if (ALIGN16) CP_COMMIT();
        }
        if (ALIGN16) { if (t + 1 < kt) CP_WAIT1(); else CP_WAIT0(); }
        __syncthreads();
        const float* cA = sAbuf[s];
        const float* cB = sBbuf[s];
        int gr = lane >> 2, gc = lane & 3;
        #pragma unroll
        for (int kk = 0; kk < 4; ++kk) {
            int c0 = kk*8 + gc;
            uint32_t ah[2][4], al[2][4];
            #pragma unroll
            for (int mt = 0; mt < 2; ++mt) {
                int r0 = warpM*32 + mt*16 + gr;
                float av[4];
                av[0] = cA[r0*SAS + c0];
                av[1] = cA[(r0+8)*SAS + c0];
                av[2] = cA[r0*SAS + c0 + 4];
                av[3] = cA[(r0+8)*SAS + c0 + 4];
                #pragma unroll
                for (int q = 0; q < 4; ++q) {
                    if (TRI) {
                        uint32_t h = __float_as_uint(av[q]) & 0xFFFFE000u;
                        ah[mt][q] = h;
                        al[mt][q] = __float_as_uint(av[q] - __uint_as_float(h));
                    } else {
                        ah[mt][q] = __float_as_uint(av[q]);
                    }
                }
            }
            #pragma unroll
            for (int nt = 0; nt < 9; ++nt) {
                int n = warpN*72 + nt*8 + gr;
                float bv[2];
                bv[0] = cB[n*SAS + c0];
                bv[1] = cB[n*SAS + c0 + 4];
                uint32_t bh[2], bl[2];
                #pragma unroll
                for (int q = 0; q < 2; ++q) {
                    if (TRI) {
                        uint32_t h = __float_as_uint(bv[q]) & 0xFFFFE000u;
                        bh[q] = h;
                        bl[q] = __float_as_uint(bv[q] - __uint_as_float(h));
                    } else {
                        bh[q] = __float_as_uint(bv[q]);
                    }
                }
                #pragma unroll
                for (int mt = 0; mt < 2; ++mt) {
                    mma_tf32(acc[mt][nt], ah[mt], bh);
                    if (TRI) {
                        mma_tf32(acc[mt][nt], ah[mt], bl);
                        mma_tf32(acc[mt][nt], al[mt], bh);
                    }
                }
            }
        }
        __syncthreads();
    }
}

// ---------------- GCN transform GEMM (standalone, writes h0) ----------------
__global__ __launch_bounds__(256, 2) void gcn_gemm_kernel(
    const float* __restrict__ A1, const float* __restrict__ B,
    float* __restrict__ C, int M, int K)
{
    extern __shared__ float smem[];
    int tid = threadIdx.x, lane = tid & 31, wid = tid >> 5;
    int warpM = wid & 3, warpN = wid >> 2;
    int m0 = blockIdx.x*128;
    float acc[2][9][4];
    #pragma unroll
    for (int i = 0; i < 2; ++i)
        #pragma unroll
        for (int j = 0; j < 9; ++j)
            #pragma unroll
            for (int q = 0; q < 4; ++q) acc[i][j][q] = 0.f;
    gemm_mainloop<true,false>(smem, A1, B, m0, M, K, tid, lane, warpM, warpN, acc);
    int gr = lane >> 2, gc2 = 2*(lane & 3);
    #pragma unroll
    for (int mt = 0; mt < 2; ++mt)
        #pragma unroll
        for (int nt = 0; nt < 9; ++nt) {
            int n = warpN*72 + nt*8 + gc2;
            if (n >= HID) continue;
            #pragma unroll
            for (int rr = 0; rr < 2; ++rr) {
                int m = m0 + warpM*32 + mt*16 + gr + rr*8;
                if (m >= M) continue;
                *(float2*)(C + (size_t)m*HID + n) =
                    make_float2(acc[mt][nt][rr*2+0], acc[mt][nt][rr*2+1]);
            }
        }
}

// ---------------- FUSED GAT transform + gate kernel ----------------
// Phase 1: xc = (relu?)(Z @ Ws^T + b_gat)  [TRI, K=528] -> SMEM
// Phase 2: logit = xc@W1 + xp@W2 + bias_fc [single tf32, two K=132 sub-GEMMs]
// Epilogue: o = sigmoid(logit)*xc + (1-sig)*xp ; LAYER 1 -> write x2 ; LAYER 2 -> pool max
template<int LAYER>
__global__ __launch_bounds__(256, 2) void fused_gat_kernel(
    const float* __restrict__ Z, const float* __restrict__ Wt,
    const float* __restrict__ bias_t,
    const float* __restrict__ xp,
    const float* __restrict__ W1, const float* __restrict__ W2,
    const float* __restrict__ bias_fc,
    float* __restrict__ Cout, const int* __restrict__ batch, int M)
{
    extern __shared__ float smem[];
    int tid = threadIdx.x, lane = tid & 31, wid = tid >> 5;
    int warpM = wid & 3, warpN = wid >> 2;
    int m0 = blockIdx.x*128;
    int gr = lane >> 2, gc = lane & 3, gc2 = 2*gc;

    float acc[2][9][4];
    #pragma unroll
    for (int i = 0; i < 2; ++i)
        #pragma unroll
        for (int j = 0; j < 9; ++j)
            #pragma unroll
            for (int q = 0; q < 4; ++q) acc[i][j][q] = 0.f;

    // ---- phase 1: transform ----
    gemm_mainloop<true,true>(smem, Z, Wt, m0, M, HH, tid, lane, warpM, warpN, acc);

    // write xc tile into SMEM [128][132], zero for rows >= M
    float* sxc = smem;
    #pragma unroll
    for (int mt = 0; mt < 2; ++mt)
        #pragma unroll
        for (int nt = 0; nt < 9; ++nt) {
            int n = warpN*72 + nt*8 + gc2;
            if (n >= HID) continue;
            float bx = bias_t[n], by = bias_t[n+1];
            #pragma unroll
            for (int rr = 0; rr < 2; ++rr) {
                int lm = warpM*32 + mt*16 + gr + rr*8;
                int m = m0 + lm;
                float v0 = acc[mt][nt][rr*2+0] + bx;
                float v1 = acc[mt][nt][rr*2+1] + by;
                if (LAYER == 1) { v0 = fmaxf(v0, 0.f); v1 = fmaxf(v1, 0.f); }
                if (m >= M) { v0 = 0.f; v1 = 0.f; }
                sxc[lm*HID + n]     = v0;
                sxc[lm*HID + n + 1] = v1;
            }
        }
    __syncthreads();

    // ---- phase 2: gate GEMM ----
    float* s2A = smem + SXC_FLOATS;
    float* s2B = s2A + SMA;
    #pragma unroll
    for (int i = 0; i < 2; ++i)
        #pragma unroll
        for (int j = 0; j < 9; ++j)
            #pragma unroll
            for (int q = 0; q < 4; ++q) acc[i][j][q] = 0.f;

    for (int sub = 0; sub < 2; ++sub) {
        const float* Bsrc = sub ? W2 : W1;
        for (int t = 0; t < 5; ++t) {
            // stage B chunk [144][32] (zfill beyond col 131)
            #pragma unroll
            for (int i = 0; i < 5; ++i) {
                int c = tid + i*256;
                if (c >= NPAD*8) break;
                int row = c >> 3, j = c & 7;
                int gk = t*32 + j*4;
                int sz = (gk < HID) ? 16 : 0;
                const float* src = sz ? Bsrc + (size_t)row*HID + gk : Bsrc;
                uint32_t dst = (uint32_t)__cvta_generic_to_shared(s2B + row*SAS + j*4);
                CP_A16(dst, src, sz);
            }
            if (sub == 1) {
                // stage A chunk from xp [128][32]
                #pragma unroll
                for (int i = 0; i < 4; ++i) {
                    int c = tid + i*256;
                    int row = c >> 3, j = c & 7;
                    int gk = t*32 + j*4;
                    int gm = m0 + row;
                    int sz = (gm < M && gk < HID) ? 16 : 0;
                    const float* src = sz ? xp + (size_t)gm*HID + gk : xp;
                    uint32_t dst = (uint32_t)__cvta_generic_to_shared(s2A + row*SAS + j*4);
                    CP_A16(dst, src, sz);
                }
            }
            CP_COMMIT();
            CP_WAIT0();
            __syncthreads();

            int ks = (t < 4) ? 4 : 1;
            for (int kk = 0; kk < ks; ++kk) {
                int c0l = kk*8 + gc;
                uint32_t ah[2][4];
                #pragma unroll
                for (int mt = 0; mt < 2; ++mt) {
                    int r0 = warpM*32 + mt*16 + gr;
                    float av[4];
                    if (sub == 0) {
                        int col = t*32 + c0l;
                        int col2 = col + 4;
                        av[0] = (col  < HID) ? sxc[r0*HID + col]      : 0.f;
                        av[1] = (col  < HID) ? sxc[(r0+8)*HID + col]  : 0.f;
                        av[2] = (col2 < HID) ? sxc[r0*HID + col2]     : 0.f;
                        av[3] = (col2 < HID) ? sxc[(r0+8)*HID + col2] : 0.f;
                    } else {
                        av[0] = s2A[r0*SAS + c0l];
                        av[1] = s2A[(r0+8)*SAS + c0l];
                        av[2] = s2A[r0*SAS + c0l + 4];
                        av[3] = s2A[(r0+8)*SAS + c0l + 4];
                    }
                    #pragma unroll
                    for (int q = 0; q < 4; ++q) ah[mt][q] = __float_as_uint(av[q]);
                }
                #pragma unroll
                for (int nt = 0; nt < 9; ++nt) {
                    int n = warpN*72 + nt*8 + gr;
                    uint32_t bh[2];
                    bh[0] = __float_as_uint(s2B[n*SAS + c0l]);
                    bh[1] = __float_as_uint(s2B[n*SAS + c0l + 4]);
                    #pragma unroll
                    for (int mt = 0; mt < 2; ++mt)
                        mma_tf32(acc[mt][nt], ah[mt], bh);
                }
            }
            __syncthreads();
        }
    }

    // ---- epilogue: gate mix ----
    #pragma unroll
    for (int mt = 0; mt < 2; ++mt)
        #pragma unroll
        for (int nt = 0; nt < 9; ++nt) {
            int n = warpN*72 + nt*8 + gc2;
            if (n >= HID) continue;
            float bx = bias_fc[n], by = bias_fc[n+1];
            #pragma unroll
            for (int rr = 0; rr < 2; ++rr) {
                int lm = warpM*32 + mt*16 + gr + rr*8;
                int m = m0 + lm;
                if (m >= M) continue;
                float z0 = 1.f / (1.f + expf(-(acc[mt][nt][rr*2+0] + bx)));
                float z1 = 1.f / (1.f + expf(-(acc[mt][nt][rr*2+1] + by)));
                float xc0 = sxc[lm*HID + n],     xc1 = sxc[lm*HID + n + 1];
                float2 xp2 = *(const float2*)(xp + (size_t)m*HID + n);
                float o0 = z0*xc0 + (1.f - z0)*xp2.x;
                float o1 = z1*xc1 + (1.f - z1)*xp2.y;
                if (LAYER == 1) {
                    *(float2*)(Cout + (size_t)m*HID + n) = make_float2(o0, o1);
                } else {
                    int bi = batch[m];
                    atomicMax(&g_pool_u[bi*HID + n],     fmap(o0));
                    atomicMax(&g_pool_u[bi*HID + n + 1], fmap(o1));
                }
            }
        }
}

// ---------------- head GEMM (32x32 tiles; optional pool decode on A) ----------------
template<bool RELU, bool DECODE>
__global__ __launch_bounds__(256) void head_gemm_kernel(
    const void* __restrict__ Ain, const float* __restrict__ B,
    const float* __restrict__ bias, float* __restrict__ C,
    int M, int N, int K)
{
    __shared__ float As[32][33];
    __shared__ float Bs[32][33];
    int tid = threadIdx.x;
    int n0 = blockIdx.x*32, m0 = blockIdx.y*32;
    int ty = tid >> 4, tx = tid & 15;
    float a00 = 0.f, a01 = 0.f, a10 = 0.f, a11 = 0.f;
    for (int k0 = 0; k0 < K; k0 += 32) {
        {
            int r = tid >> 3, j = (tid & 7)*4;
            int gm = m0 + r;
            #pragma unroll
            for (int q = 0; q < 4; ++q) {
                int gk = k0 + j + q;
                float v = 0.f;
                if (gm < M && gk < K) {
                    if (DECODE) v = fmap_inv(((const unsigned*)Ain)[gm*K + gk]);
                    else        v = ((const float*)Ain)[gm*K + gk];
                }
                As[j + q][r] = v;
            }
            int kk = tid >> 3, jn = (tid & 7)*4;
            #pragma unroll
            for (int q = 0; q < 4; ++q) {
                int gn = n0 + jn + q;
                int gk = k0 + kk;
                Bs[kk][jn + q] = (gk < K && gn < N) ? B[(size_t)gk*N + gn] : 0.f;
            }
        }
        __syncthreads();
        #pragma unroll
        for (int k = 0; k < 32; ++k) {
            float av0 = As[k][2*ty], av1 = As[k][2*ty+1];
            float bv0 = Bs[k][2*tx], bv1 = Bs[k][2*tx+1];
            a00 += av0*bv0; a01 += av0*bv1;
            a10 += av1*bv0; a11 += av1*bv1;
        }
        __syncthreads();
    }
    int m = m0 + 2*ty, n = n0 + 2*tx;
    if (m < M && n < N) {
        float b0 = bias[n], b1 = bias[n+1];
        float v00 = a00 + b0, v01 = a01 + b1, v10 = a10 + b0, v11 = a11 + b1;
        if (RELU) { v00 = fmaxf(v00,0.f); v01 = fmaxf(v01,0.f); v10 = fmaxf(v10,0.f); v11 = fmaxf(v11,0.f); }
        C[(size_t)m*N + n] = v00; C[(size_t)m*N + n + 1] = v01;
        if (m + 1 < M) { C[(size_t)(m+1)*N + n] = v10; C[(size_t)(m+1)*N + n + 1] = v11; }
    }
}

// ---------------- launch ----------------
extern "C" void kernel_launch(void* const* d_in, const int* in_sizes, int n_in,
                              void* d_out, int out_size) {
    const float* x        = (const float*)d_in[0];
    const int*   ei       = (const int*)  d_in[1];
    const float* ew       = (const float*)d_in[2];
    const int*   batch    = (const int*)  d_in[3];
    const float* W_gcn    = (const float*)d_in[4];
    const float* b_gcn    = (const float*)d_in[5];
    const float* W_gat1   = (const float*)d_in[6];
    const float* a_src1   = (const float*)d_in[7];
    const float* a_dst1   = (const float*)d_in[8];
    const float* b_gat1   = (const float*)d_in[9];
    const float* W_gat2   = (const float*)d_in[10];
    const float* a_src2   = (const float*)d_in[11];
    const float* a_dst2   = (const float*)d_in[12];
    const float* b_gat2   = (const float*)d_in[13];
    const float* W_fc1    = (const float*)d_in[14];
    const float* b_fc1    = (const float*)d_in[15];
    const float* W_fc2    = (const float*)d_in[16];
    const float* b_fc2    = (const float*)d_in[17];
    const float* pro_bias = (const float*)d_in[18];
    const float* W_g1     = (const float*)d_in[19];
    const float* b_g1     = (const float*)d_in[20];
    const float* W_g2     = (const float*)d_in[21];
    const float* b_g2     = (const float*)d_in[22];
    float* out = (float*)d_out;

    float *p_h0, *p_x1, *p_x2, *p_Z, *p_hid, *p_bias_fc, *p_wesd1, *p_wesd2;
    float *p_wgcn, *p_ws1, *p_ws2, *p_wfc1, *p_wfc2;
    unsigned* p_pool_u;
    cudaGetSymbolAddress((void**)&p_h0,   g_h0);
    cudaGetSymbolAddress((void**)&p_x1,   g_x1);
    cudaGetSymbolAddress((void**)&p_x2,   g_x2);
    cudaGetSymbolAddress((void**)&p_Z,    g_Z);
    cudaGetSymbolAddress((void**)&p_hid,  g_hid);
    cudaGetSymbolAddress((void**)&p_bias_fc, g_bias_fc);
    cudaGetSymbolAddress((void**)&p_wesd1, g_wesd1);
    cudaGetSymbolAddress((void**)&p_wesd2, g_wesd2);
    cudaGetSymbolAddress((void**)&p_wgcn, g_wgcn);
    cudaGetSymbolAddress((void**)&p_ws1,  g_ws1);
    cudaGetSymbolAddress((void**)&p_ws2,  g_ws2);
    cudaGetSymbolAddress((void**)&p_wfc1, g_wfc1);
    cudaGetSymbolAddress((void**)&p_wfc2, g_wfc2);
    cudaGetSymbolAddress((void**)&p_pool_u, g_pool_u);

    static bool attr_done = false;
    if (!attr_done) {
        cudaFuncSetAttribute(gcn_gemm_kernel, cudaFuncAttributeMaxDynamicSharedMemorySize, SMEM_GEMM_BYTES);
        cudaFuncSetAttribute(fused_gat_kernel<1>, cudaFuncAttributeMaxDynamicSharedMemorySize, SMEM_FUSED_BYTES);
        cudaFuncSetAttribute(fused_gat_kernel<2>, cudaFuncAttributeMaxDynamicSharedMemorySize, SMEM_FUSED_BYTES);
        attr_done = true;
    }

    const int TB = 256;
    const int MT = (NN + 127)/128;   // 235
    dim3 ggrid(MT, 1);

    // slots 1-3: independent prep; slot 4 = GCN GEMM (profiled)
    prep_Wgcn_kernel<<<(NPAD*FIN+TB-1)/TB, TB>>>(W_gcn);
    zero_cnt_pool_kernel<<<(NN+TB-1)/TB, TB>>>();
    hist_kernel<<<(EE+TB-1)/TB, TB>>>(ei);
    gcn_gemm_kernel<<<ggrid, 256, SMEM_GEMM_BYTES>>>(x, p_wgcn, p_h0, NN, FIN);
    // CSR chain
    scan_kernel<<<1, 1024>>>();
    fill_kernel<<<(EE+TB-1)/TB, TB>>>(ei);
    deg_kernel<<<(NN*32+TB-1)/TB, TB>>>(ew);
    // weight prep
    prep_Wstack2_kernel<<<(2*NPAD*HH+TB-1)/TB, TB>>>(W_gat1, W_gat2);
    prep_Wfc12_kernel<<<(2*NPAD*HID+TB-1)/TB, TB>>>(W_fc1, W_fc2);
    prep_esd_bias_kernel<<<(2*HID*8+HID+TB-1)/TB, TB>>>(W_gat1, a_src1, a_dst1,
                                                        W_gat2, a_src2, a_dst2,
                                                        b_fc1, b_fc2, pro_bias);

    // layer 0
    gcn_agg_kernel<<<NN, HID>>>(ew, b_gcn);

    // layer 1: scores -> aggregate -> fused transform+gate -> x2
    esd_kernel<<<(NN*32+TB-1)/TB, TB>>>(p_x1, p_wesd1);
    gat_aggz_kernel<<<NN, 160>>>(p_x1);
    fused_gat_kernel<1><<<ggrid, 256, SMEM_FUSED_BYTES>>>(p_Z, p_ws1, b_gat1, p_x1,
                                                          p_wfc1, p_wfc2, p_bias_fc,
                                                          p_x2, nullptr, NN);

    // layer 2: scores -> aggregate -> fused transform+gate -> pool max
    esd_kernel<<<(NN*32+TB-1)/TB, TB>>>(p_x2, p_wesd2);
    gat_aggz_kernel<<<NN, 160>>>(p_x2);
    fused_gat_kernel<2><<<ggrid, 256, SMEM_FUSED_BYTES>>>(p_Z, p_ws2, b_gat2, p_x2,
                                                          p_wfc1, p_wfc2, p_bias_fc,
                                                          nullptr, batch, NN);

    // head: pool (decoded inline) -> relu fc -> out
    head_gemm_kernel<true, true ><<<dim3(GFC/32, GG/32), 256>>>(p_pool_u, W_g1, b_g1, p_hid, GG, GFC, HID);
    head_gemm_kernel<false,false><<<dim3(OUTD/32, GG/32), 256>>>(p_hid, W_g2, b_g2, out, GG, OUTD, GFC);
}

// round 11
// speedup vs baseline: 1.1573x; 1.0519x over previous
#include <cuda_runtime.h>
#include <math.h>
#include <stdint.h>

// ---------------- problem constants ----------------
#define NN    30000
#define EE    300000
#define FIN   33
#define HID   132
#define HEADS 4
#define HH    528
#define GG    64
#define GFC   1024
#define OUTD  128
#define NPAD  144

// ---------------- scratch (device globals) ----------------
__device__ __align__(16) float g_dis[NN];
__device__ int   g_cnt[NN];
__device__ int   g_off[NN+1];
__device__ int   g_cur[NN];
__device__ int   g_csr_src[EE];
__device__ int   g_csr_eid[EE];
__device__ __align__(16) float g_h0[NN*HID];
__device__ __align__(16) float g_x1[NN*HID];
__device__ __align__(16) float g_x2[NN*HID];
__device__ __align__(16) float g_Z[NN*HH];
__device__ __align__(16) float g_es[NN*HEADS];
__device__ __align__(16) float g_ed[NN*HEADS];
__device__ unsigned g_pool_u[GG*HID];
__device__ __align__(16) float g_hid[GG*GFC];
__device__ __align__(16) float g_wesd1[HID*8];
__device__ __align__(16) float g_wesd2[HID*8];
// fp32 prepped weights
__device__ __align__(16) float g_wgcn[NPAD*FIN];
__device__ __align__(16) float g_ws1[NPAD*HH];
__device__ __align__(16) float g_ws2[NPAD*HH];
__device__ __align__(16) float g_wfc1[NPAD*HID];
__device__ __align__(16) float g_wfc2[NPAD*HID];
__device__ float g_bias_fc[HID];

// ---------------- CSR build ----------------
__global__ void zero_cnt_pool_kernel() {
    int i = blockIdx.x*blockDim.x + threadIdx.x;
    if (i < NN) g_cnt[i] = 0;
    if (i < GG*HID) g_pool_u[i] = 0u;
}
__global__ void hist_kernel(const int* __restrict__ ei) {
    int e = blockIdx.x*blockDim.x + threadIdx.x;
    if (e < EE) atomicAdd(&g_cnt[ei[EE + e]], 1);
}
__global__ void scan_kernel() {
    const int CH = (NN + 1023) / 1024;
    __shared__ int ssum[1024];
    int t = threadIdx.x;
    int c0 = t*CH, c1 = min(c0+CH, NN);
    int s = 0;
    for (int i = c0; i < c1; ++i) s += g_cnt[i];
    ssum[t] = s;
    __syncthreads();
    for (int d = 1; d < 1024; d <<= 1) {
        int v = (t >= d) ? ssum[t-d] : 0;
        __syncthreads();
        ssum[t] += v;
        __syncthreads();
    }
    int run = (t == 0) ? 0 : ssum[t-1];
    for (int i = c0; i < c1; ++i) { g_off[i] = run; g_cur[i] = run; run += g_cnt[i]; }
    if (t == 0) g_off[NN] = ssum[1023];
}
__global__ void fill_kernel(const int* __restrict__ ei) {
    int e = blockIdx.x*blockDim.x + threadIdx.x;
    if (e >= EE) return;
    int d = ei[EE + e];
    int p = atomicAdd(&g_cur[d], 1);
    g_csr_src[p] = ei[e];
    g_csr_eid[p] = e;
}
__global__ void deg_kernel(const float* __restrict__ ew) {
    int gw = (blockIdx.x*blockDim.x + threadIdx.x) >> 5;
    int lane = threadIdx.x & 31;
    if (gw >= NN) return;
    int b0 = g_off[gw], b1 = g_off[gw+1];
    float s = 0.f;
    for (int j = b0 + lane; j < b1; j += 32) s += ew[g_csr_eid[j]];
    #pragma unroll
    for (int o = 16; o; o >>= 1) s += __shfl_down_sync(0xffffffffu, s, o);
    if (lane == 0) g_dis[gw] = rsqrtf(1.f + s);
}

// ---------------- weight prep ----------------
__global__ void prep_Wgcn_kernel(const float* __restrict__ W) {
    int i = blockIdx.x*blockDim.x + threadIdx.x;
    if (i >= NPAD*FIN) return;
    int n = i / FIN, k = i % FIN;
    g_wgcn[i] = (n < HID) ? W[k*HID + n] : 0.f;
}
__global__ void prep_Wstack2_kernel(const float* __restrict__ W1, const float* __restrict__ W2) {
    int i = blockIdx.x*blockDim.x + threadIdx.x;
    if (i >= 2*NPAD*HH) return;
    const float* W = (i < NPAD*HH) ? W1 : W2;
    float* out = (i < NPAD*HH) ? g_ws1 : g_ws2;
    int j = (i < NPAD*HH) ? i : i - NPAD*HH;
    int n = j / HH, k = j % HH;
    float v = 0.f;
    if (n < HID) {
        int h = k / HID, kk = k % HID;
        v = 0.25f * W[kk*HH + h*HID + n];
    }
    out[j] = v;
}
__global__ void prep_Wfc12_kernel(const float* __restrict__ W1, const float* __restrict__ W2) {
    int i = blockIdx.x*blockDim.x + threadIdx.x;
    if (i >= 2*NPAD*HID) return;
    const float* W = (i < NPAD*HID) ? W1 : W2;
    float* out = (i < NPAD*HID) ? g_wfc1 : g_wfc2;
    int j = (i < NPAD*HID) ? i : i - NPAD*HID;
    int n = j / HID, k = j % HID;
    out[j] = (n < HID) ? W[k*HID + n] : 0.f;
}
__global__ void prep_esd_bias_kernel(const float* __restrict__ W1,
                                     const float* __restrict__ as1, const float* __restrict__ ad1,
                                     const float* __restrict__ W2,
                                     const float* __restrict__ as2, const float* __restrict__ ad2,
                                     const float* __restrict__ b1, const float* __restrict__ b2,
                                     const float* __restrict__ pro) {
    int i = blockIdx.x*blockDim.x + threadIdx.x;
    if (i < 2*HID*8) {
        const float* W = (i < HID*8) ? W1 : W2;
        const float* as = (i < HID*8) ? as1 : as2;
        const float* ad = (i < HID*8) ? ad1 : ad2;
        float* out = (i < HID*8) ? g_wesd1 : g_wesd2;
        int j = (i < HID*8) ? i : i - HID*8;
        int k = j >> 3, q = j & 7, h = q >> 1;
        const float* a = (q & 1) ? ad : as;
        float s = 0.f;
        for (int c = 0; c < HID; ++c) s += W[k*HH + h*HID + c] * a[h*HID + c];
        out[j] = s;
    } else if (i < 2*HID*8 + HID) {
        int c = i - 2*HID*8;
        g_bias_fc[c] = b1[c] + b2[c] + pro[c];
    }
}

__device__ __forceinline__ float lrelu02(float v) { return v > 0.f ? v : 0.2f*v; }

// ---------------- GCN aggregation + fused layer-1 score computation ----------------
__global__ __launch_bounds__(160) void gcn_agg_kernel(const float* __restrict__ ew,
                                                      const float* __restrict__ bias) {
    __shared__ float snorm[64];
    __shared__ int   ssrc[64];
    __shared__ float sx[HID];
    int n = blockIdx.x, tid = threadIdx.x;
    int b0 = g_off[n], b1 = g_off[n+1];
    int deg = b1 - b0;
    float dn = g_dis[n];
    if (tid < 64 && tid < deg) {
        int j = b0 + tid;
        int s = g_csr_src[j];
        snorm[tid] = g_dis[s] * ew[g_csr_eid[j]] * dn;
        ssrc[tid] = s;
    }
    __syncthreads();
    if (tid < HID) {
        float acc = bias[tid] + dn*dn*g_h0[n*HID + tid];
        int lim = min(deg, 64);
        for (int t = 0; t < lim; ++t)
            acc += snorm[t] * g_h0[ssrc[t]*HID + tid];
        for (int j = b0 + 64; j < b1; ++j) {   // rare fallback
            int s = g_csr_src[j];
            acc += g_dis[s] * ew[g_csr_eid[j]] * dn * g_h0[s*HID + tid];
        }
        acc = fmaxf(acc, 0.f);
        g_x1[n*HID + tid] = acc;
        sx[tid] = acc;
    }
    __syncthreads();
    // layer-1 scores: es/ed = x1[n] @ wesd1
    if (tid < 32) {
        float p[8] = {0,0,0,0,0,0,0,0};
        for (int c = tid; c < HID; c += 32) {
            float xv = sx[c];
            const float* wr = g_wesd1 + c*8;
            #pragma unroll
            for (int q = 0; q < 8; ++q) p[q] += xv * wr[q];
        }
        #pragma unroll
        for (int q = 0; q < 8; ++q)
            #pragma unroll
            for (int o = 16; o; o >>= 1) p[q] += __shfl_down_sync(0xffffffffu, p[q], o);
        if (tid == 0) {
            ((float4*)g_es)[n] = make_float4(p[0], p[2], p[4], p[6]);
            ((float4*)g_ed)[n] = make_float4(p[1], p[3], p[5], p[7]);
        }
    }
}

// ---------------- GAT aggregate-first (single exp per edge-head) ----------------
__global__ __launch_bounds__(160) void gat_aggz_kernel(const float* __restrict__ xin) {
    __shared__ float4 sexp[64];
    __shared__ int    ssrc[64];
    __shared__ float4 s_inv;
    __shared__ float4 s_selfw;
    int n = blockIdx.x, tid = threadIdx.x;
    int b0 = g_off[n], b1 = g_off[n+1];
    int deg = b1 - b0;
    float4 edn = ((float4*)g_ed)[n];
    // phase A: edge exps (first 64 edges cached)
    if (tid < 64) {
        float4 v = make_float4(0.f, 0.f, 0.f, 0.f);
        int s = 0;
        if (tid < deg) {
            s = g_csr_src[b0 + tid];
            float4 e4 = ((float4*)g_es)[s];
            v.x = __expf(lrelu02(e4.x + edn.x));
            v.y = __expf(lrelu02(e4.y + edn.y));
            v.z = __expf(lrelu02(e4.z + edn.z));
            v.w = __expf(lrelu02(e4.w + edn.w));
        }
        sexp[tid] = v;
        ssrc[tid] = s;
    }
    __syncthreads();
    // phase B: warp 0 reduces denominators; computes self-exp + inverses once
    if (tid < 32) {
        float4 a = sexp[tid], b = sexp[tid + 32];
        float4 ds = make_float4(a.x + b.x, a.y + b.y, a.z + b.z, a.w + b.w);
        for (int j = b0 + 64 + tid; j < b1; j += 32) {   // rare fallback
            int s = g_csr_src[j];
            float4 e4 = ((float4*)g_es)[s];
            ds.x += __expf(lrelu02(e4.x + edn.x));
            ds.y += __expf(lrelu02(e4.y + edn.y));
            ds.z += __expf(lrelu02(e4.z + edn.z));
            ds.w += __expf(lrelu02(e4.w + edn.w));
        }
        #pragma unroll
        for (int o = 16; o; o >>= 1) {
            ds.x += __shfl_down_sync(0xffffffffu, ds.x, o);
            ds.y += __shfl_down_sync(0xffffffffu, ds.y, o);
            ds.z += __shfl_down_sync(0xffffffffu, ds.z, o);
            ds.w += __shfl_down_sync(0xffffffffu, ds.w, o);
        }
        if (tid == 0) {
            float4 en = ((float4*)g_es)[n];
            float sx = __expf(lrelu02(en.x + edn.x));
            float sy = __expf(lrelu02(en.y + edn.y));
            float sz = __expf(lrelu02(en.z + edn.z));
            float sw = __expf(lrelu02(en.w + edn.w));
            float ix = 1.f/(ds.x + sx), iy = 1.f/(ds.y + sy);
            float iz = 1.f/(ds.z + sz), iw = 1.f/(ds.w + sw);
            s_inv = make_float4(ix, iy, iz, iw);
            s_selfw = make_float4(sx*ix, sy*iy, sz*iz, sw*iw);
        }
    }
    __syncthreads();
    // phase C: normalize cached exps -> alphas
    float4 inv = s_inv;
    if (tid < 64) {
        float4 v = sexp[tid];
        v.x *= inv.x; v.y *= inv.y; v.z *= inv.z; v.w *= inv.w;
        sexp[tid] = v;
    }
    __syncthreads();
    // phase D: aggregate
    if (tid < HID) {
        float4 sw = s_selfw;
        float xv0 = xin[n*HID + tid];
        float acc0 = sw.x*xv0, acc1 = sw.y*xv0, acc2 = sw.z*xv0, acc3 = sw.w*xv0;
        int lim = min(deg, 64);
        for (int t = 0; t < lim; ++t) {
            float xv = xin[ssrc[t]*HID + tid];
            float4 al = sexp[t];
            acc0 += al.x*xv; acc1 += al.y*xv; acc2 += al.z*xv; acc3 += al.w*xv;
        }
        for (int j = b0 + 64; j < b1; ++j) {   // rare fallback
            int s = g_csr_src[j];
            float4 e4 = ((float4*)g_es)[s];
            float xv = xin[s*HID + tid];
            acc0 += __expf(lrelu02(e4.x + edn.x))*inv.x*xv;
            acc1 += __expf(lrelu02(e4.y + edn.y))*inv.y*xv;
            acc2 += __expf(lrelu02(e4.z + edn.z))*inv.z*xv;
            acc3 += __expf(lrelu02(e4.w + edn.w))*inv.w*xv;
        }
        float* zp = g_Z + (size_t)n*HH;
        zp[tid]         = acc0;
        zp[HID + tid]   = acc1;
        zp[2*HID + tid] = acc2;
        zp[3*HID + tid] = acc3;
    }
}

// ---------------- GEMM common ----------------
#define SAS 36
#define SMA (128*SAS)
#define SMB (NPAD*SAS)
#define SMEM_GEMM_BYTES ((2*SMA + 2*SMB)*4)   // 78336
#define SXC_FLOATS (128*HID)
#define SMEM_FUSED_BYTES ((SXC_FLOATS + SMA + SMB)*4)   // 106752

#define CP_A16(dst, src, sz) asm volatile("cp.async.ca.shared.global [%0], [%1], 16, %2;" :: "r"(dst), "l"(src), "r"(sz) : "memory")
#define CP_COMMIT() asm volatile("cp.async.commit_group;" ::: "memory")
#define CP_WAIT1()  asm volatile("cp.async.wait_group 1;" ::: "memory")
#define CP_WAIT0()  asm volatile("cp.async.wait_group 0;" ::: "memory")

__device__ __forceinline__ void mma_tf32(float* d, const uint32_t* a, const uint32_t* b) {
    asm volatile("mma.sync.aligned.m16n8k8.row.col.f32.tf32.tf32.f32 "
        "{%0,%1,%2,%3}, {%4,%5,%6,%7}, {%8,%9}, {%0,%1,%2,%3};"
        : "+f"(d[0]), "+f"(d[1]), "+f"(d[2]), "+f"(d[3])
        : "r"(a[0]), "r"(a[1]), "r"(a[2]), "r"(a[3]), "r"(b[0]), "r"(b[1]));
}
__device__ __forceinline__ unsigned fmap(float f) {
    unsigned u = __float_as_uint(f);
    return (u & 0x80000000u) ? ~u : (u | 0x80000000u);
}
__device__ __forceinline__ float fmap_inv(unsigned u) {
    return (u & 0x80000000u) ? __uint_as_float(u ^ 0x80000000u) : __uint_as_float(~u);
}

template<bool ALIGN16>
__device__ __forceinline__ void load_tile(
    float* sA, float* sB, const float* A1, const float* B,
    int m0, int k0, int M, int K, int tid)
{
    if (ALIGN16) {
        #pragma unroll
        for (int i = 0; i < 4; ++i) {
            int c = tid + i*256;
            int row = c >> 3, j = c & 7;
            int gm = m0 + row, gk = k0 + j*4;
            int sz = (gm < M && gk < K) ? 16 : 0;
            const float* src = sz ? A1 + (size_t)gm*K + gk : A1;
            uint32_t dst = (uint32_t)__cvta_generic_to_shared(sA + row*SAS + j*4);
            CP_A16(dst, src, sz);
        }
        #pragma unroll
        for (int i = 0; i < 5; ++i) {
            int c = tid + i*256;
            if (c >= NPAD*8) break;
            int row = c >> 3, j = c & 7;
            int gk = k0 + j*4;
            int sz = (gk < K) ? 16 : 0;
            const float* src = sz ? B + (size_t)row*K + gk : B;
            uint32_t dst = (uint32_t)__cvta_generic_to_shared(sB + row*SAS + j*4);
            CP_A16(dst, src, sz);
        }
    } else {
        #pragma unroll
        for (int i = 0; i < 4; ++i) {
            int c = tid + i*256;
            int row = c >> 3, j = c & 7;
            int gm = m0 + row;
            #pragma unroll
            for (int q = 0; q < 4; ++q) {
                int gk = k0 + j*4 + q;
                sA[row*SAS + j*4 + q] = (gm < M && gk < K) ? A1[(size_t)gm*K + gk] : 0.f;
            }
        }
        #pragma unroll
        for (int i = 0; i < 5; ++i) {
            int c = tid + i*256;
            if (c >= NPAD*8) break;
            int row = c >> 3, j = c & 7;
            #pragma unroll
            for (int q = 0; q < 4; ++q) {
                int gk = k0 + j*4 + q;
                sB[row*SAS + j*4 + q] = (gk < K) ? B[(size_t)row*K + gk] : 0.f;
            }
        }
    }
}

template<bool TRI, bool ALIGN16>
__device__ __forceinline__ void gemm_mainloop(
    float* smem, const float* A1, const float* B,
    int m0, int M, int K, int tid, int lane, int warpM, int warpN,
    float acc[2][9][4])
{
    float* sAbuf[2] = { smem, smem + SMA };
    float* sBbuf[2] = { smem + 2*SMA, smem + 2*SMA + SMB };
    int kt = (K + 31) >> 5;
    load_tile<ALIGN16>(sAbuf[0], sBbuf[0], A1, B, m0, 0, M, K, tid);
    if (ALIGN16) CP_COMMIT();
    for (int t = 0; t < kt; ++t) {
        int s = t & 1;
        if (t + 1 < kt) {
            load_tile<ALIGN16>(sAbuf[s^1], sBbuf[s^1], A1, B, m0, (t+1)*32, M, K, tid);
            if (ALIGN16) CP_COMMIT();
        }
        if (ALIGN16) { if (t + 1 < kt) CP_WAIT1(); else CP_WAIT0(); }
        __syncthreads();
        const float* cA = sAbuf[s];
        const float* cB = sBbuf[s];
        int gr = lane >> 2, gc = lane & 3;
        #pragma unroll
        for (int kk = 0; kk < 4; ++kk) {
            int c0 = kk*8 + gc;
            uint32_t ah[2][4], al[2][4];
            #pragma unroll
            for (int mt = 0; mt < 2; ++mt) {
                int r0 = warpM*32 + mt*16 + gr;
                float av[4];
                av[0] = cA[r0*SAS + c0];
                av[1] = cA[(r0+8)*SAS + c0];
                av[2] = cA[r0*SAS + c0 + 4];
                av[3] = cA[(r0+8)*SAS + c0 + 4];
                #pragma unroll
                for (int q = 0; q < 4; ++q) {
                    if (TRI) {
                        uint32_t h = __float_as_uint(av[q]) & 0xFFFFE000u;
                        ah[mt][q] = h;
                        al[mt][q] = __float_as_uint(av[q] - __uint_as_float(h));
                    } else {
                        ah[mt][q] = __float_as_uint(av[q]);
                    }
                }
            }
            #pragma unroll
            for (int nt = 0; nt < 9; ++nt) {
                int n = warpN*72 + nt*8 + gr;
                float bv[2];
                bv[0] = cB[n*SAS + c0];
                bv[1] = cB[n*SAS + c0 + 4];
                uint32_t bh[2], bl[2];
                #pragma unroll
                for (int q = 0; q < 2; ++q) {
                    if (TRI) {
                        uint32_t h = __float_as_uint(bv[q]) & 0xFFFFE000u;
                        bh[q] = h;
                        bl[q] = __float_as_uint(bv[q] - __uint_as_float(h));
                    } else {
                        bh[q] = __float_as_uint(bv[q]);
                    }
                }
                #pragma unroll
                for (int mt = 0; mt < 2; ++mt) {
                    mma_tf32(acc[mt][nt], ah[mt], bh);
                    if (TRI) {
                        mma_tf32(acc[mt][nt], ah[mt], bl);
                        mma_tf32(acc[mt][nt], al[mt], bh);
                    }
                }
            }
        }
        __syncthreads();
    }
}

// ---------------- GCN transform GEMM ----------------
__global__ __launch_bounds__(256, 2) void gcn_gemm_kernel(
    const float* __restrict__ A1, const float* __restrict__ B,
    float* __restrict__ C, int M, int K)
{
    extern __shared__ float smem[];
    int tid = threadIdx.x, lane = tid & 31, wid = tid >> 5;
    int warpM = wid & 3, warpN = wid >> 2;
    int m0 = blockIdx.x*128;
    float acc[2][9][4];
    #pragma unroll
    for (int i = 0; i < 2; ++i)
        #pragma unroll
        for (int j = 0; j < 9; ++j)
            #pragma unroll
            for (int q = 0; q < 4; ++q) acc[i][j][q] = 0.f;
    gemm_mainloop<true,false>(smem, A1, B, m0, M, K, tid, lane, warpM, warpN, acc);
    int gr = lane >> 2, gc2 = 2*(lane & 3);
    #pragma unroll
    for (int mt = 0; mt < 2; ++mt)
        #pragma unroll
        for (int nt = 0; nt < 9; ++nt) {
            int n = warpN*72 + nt*8 + gc2;
            if (n >= HID) continue;
            #pragma unroll
            for (int rr = 0; rr < 2; ++rr) {
                int m = m0 + warpM*32 + mt*16 + gr + rr*8;
                if (m >= M) continue;
                *(float2*)(C + (size_t)m*HID + n) =
                    make_float2(acc[mt][nt][rr*2+0], acc[mt][nt][rr*2+1]);
            }
        }
}

// ---------------- FUSED GAT transform + gate (+ next-layer scores) ----------------
template<int LAYER>
__global__ __launch_bounds__(256, 2) void fused_gat_kernel(
    const float* __restrict__ Z, const float* __restrict__ Wt,
    const float* __restrict__ bias_t,
    const float* __restrict__ xp,
    const float* __restrict__ W1, const float* __restrict__ W2,
    const float* __restrict__ bias_fc,
    const float* __restrict__ wesd_next,
    float* __restrict__ Cout, const int* __restrict__ batch, int M)
{
    extern __shared__ float smem[];
    int tid = threadIdx.x, lane = tid & 31, wid = tid >> 5;
    int warpM = wid & 3, warpN = wid >> 2;
    int m0 = blockIdx.x*128;
    int gr = lane >> 2, gc = lane & 3, gc2 = 2*gc;

    float acc[2][9][4];
    #pragma unroll
    for (int i = 0; i < 2; ++i)
        #pragma unroll
        for (int j = 0; j < 9; ++j)
            #pragma unroll
            for (int q = 0; q < 4; ++q) acc[i][j][q] = 0.f;

    // phase 1: transform (TRI, K=528)
    gemm_mainloop<true,true>(smem, Z, Wt, m0, M, HH, tid, lane, warpM, warpN, acc);

    // xc tile -> SMEM
    float* sxc = smem;
    #pragma unroll
    for (int mt = 0; mt < 2; ++mt)
        #pragma unroll
        for (int nt = 0; nt < 9; ++nt) {
            int n = warpN*72 + nt*8 + gc2;
            if (n >= HID) continue;
            float bx = bias_t[n], by = bias_t[n+1];
            #pragma unroll
            for (int rr = 0; rr < 2; ++rr) {
                int lm = warpM*32 + mt*16 + gr + rr*8;
                int m = m0 + lm;
                float v0 = acc[mt][nt][rr*2+0] + bx;
                float v1 = acc[mt][nt][rr*2+1] + by;
                if (LAYER == 1) { v0 = fmaxf(v0, 0.f); v1 = fmaxf(v1, 0.f); }
                if (m >= M) { v0 = 0.f; v1 = 0.f; }
                sxc[lm*HID + n]     = v0;
                sxc[lm*HID + n + 1] = v1;
            }
        }
    __syncthreads();

    // phase 2: gate GEMM (single tf32, K = 132 + 132)
    float* s2A = smem + SXC_FLOATS;
    float* s2B = s2A + SMA;
    #pragma unroll
    for (int i = 0; i < 2; ++i)
        #pragma unroll
        for (int j = 0; j < 9; ++j)
            #pragma unroll
            for (int q = 0; q < 4; ++q) acc[i][j][q] = 0.f;

    for (int sub = 0; sub < 2; ++sub) {
        const float* Bsrc = sub ? W2 : W1;
        for (int t = 0; t < 5; ++t) {
            #pragma unroll
            for (int i = 0; i < 5; ++i) {
                int c = tid + i*256;
                if (c >= NPAD*8) break;
                int row = c >> 3, j = c & 7;
                int gk = t*32 + j*4;
                int sz = (gk < HID) ? 16 : 0;
                const float* src = sz ? Bsrc + (size_t)row*HID + gk : Bsrc;
                uint32_t dst = (uint32_t)__cvta_generic_to_shared(s2B + row*SAS + j*4);
                CP_A16(dst, src, sz);
            }
            if (sub == 1) {
                #pragma unroll
                for (int i = 0; i < 4; ++i) {
                    int c = tid + i*256;
                    int row = c >> 3, j = c & 7;
                    int gk = t*32 + j*4;
                    int gm = m0 + row;
                    int sz = (gm < M && gk < HID) ? 16 : 0;
                    const float* src = sz ? xp + (size_t)gm*HID + gk : xp;
                    uint32_t dst = (uint32_t)__cvta_generic_to_shared(s2A + row*SAS + j*4);
                    CP_A16(dst, src, sz);
                }
            }
            CP_COMMIT();
            CP_WAIT0();
            __syncthreads();

            int ks = (t < 4) ? 4 : 1;
            for (int kk = 0; kk < ks; ++kk) {
                int c0l = kk*8 + gc;
                uint32_t ah[2][4];
                #pragma unroll
                for (int mt = 0; mt < 2; ++mt) {
                    int r0 = warpM*32 + mt*16 + gr;
                    float av[4];
                    if (sub == 0) {
                        int col = t*32 + c0l;
                        int col2 = col + 4;
                        av[0] = (col  < HID) ? sxc[r0*HID + col]      : 0.f;
                        av[1] = (col  < HID) ? sxc[(r0+8)*HID + col]  : 0.f;
                        av[2] = (col2 < HID) ? sxc[r0*HID + col2]     : 0.f;
                        av[3] = (col2 < HID) ? sxc[(r0+8)*HID + col2] : 0.f;
                    } else {
                        av[0] = s2A[r0*SAS + c0l];
                        av[1] = s2A[(r0+8)*SAS + c0l];
                        av[2] = s2A[r0*SAS + c0l + 4];
                        av[3] = s2A[(r0+8)*SAS + c0l + 4];
                    }
                    #pragma unroll
                    for (int q = 0; q < 4; ++q) ah[mt][q] = __float_as_uint(av[q]);
                }
                #pragma unroll
                for (int nt = 0; nt < 9; ++nt) {
                    int n = warpN*72 + nt*8 + gr;
                    uint32_t bh[2];
                    bh[0] = __float_as_uint(s2B[n*SAS + c0l]);
                    bh[1] = __float_as_uint(s2B[n*SAS + c0l + 4]);
                    #pragma unroll
                    for (int mt = 0; mt < 2; ++mt)
                        mma_tf32(acc[mt][nt], ah[mt], bh);
                }
            }
            __syncthreads();
        }
    }

    // stage wesd_next into SMEM (s2B area is free) for the score reduction
    if (LAYER == 1) {
        for (int i = tid; i < HID*8; i += 256) s2B[i] = wesd_next[i];
    }

    // epilogue: gate mix; store o back into sxc for score reduction
    #pragma unroll
    for (int mt = 0; mt < 2; ++mt)
        #pragma unroll
        for (int nt = 0; nt < 9; ++nt) {
            int n = warpN*72 + nt*8 + gc2;
            if (n >= HID) continue;
            float bx = bias_fc[n], by = bias_fc[n+1];
            #pragma unroll
            for (int rr = 0; rr < 2; ++rr) {
                int lm = warpM*32 + mt*16 + gr + rr*8;
                int m = m0 + lm;
                if (m >= M) continue;
                float z0 = 1.f / (1.f + __expf(-(acc[mt][nt][rr*2+0] + bx)));
                float z1 = 1.f / (1.f + __expf(-(acc[mt][nt][rr*2+1] + by)));
                float xc0 = sxc[lm*HID + n],     xc1 = sxc[lm*HID + n + 1];
                float2 xp2 = *(const float2*)(xp + (size_t)m*HID + n);
                float o0 = z0*xc0 + (1.f - z0)*xp2.x;
                float o1 = z1*xc1 + (1.f - z1)*xp2.y;
                if (LAYER == 1) {
                    *(float2*)(Cout + (size_t)m*HID + n) = make_float2(o0, o1);
                    sxc[lm*HID + n]     = o0;
                    sxc[lm*HID + n + 1] = o1;
                } else {
                    int bi = batch[m];
                    atomicMax(&g_pool_u[bi*HID + n],     fmap(o0));
                    atomicMax(&g_pool_u[bi*HID + n + 1], fmap(o1));
                }
            }
        }

    // layer-2 scores from the o tile (LAYER 1 only)
    if (LAYER == 1) {
        __syncthreads();
        for (int r = 0; r < 16; ++r) {
            int lm = wid*16 + r;
            int m = m0 + lm;
            if (m >= M) continue;
            float p[8] = {0,0,0,0,0,0,0,0};
            for (int c = lane; c < HID; c += 32) {
                float xv = sxc[lm*HID + c];
                const float* wr = s2B + c*8;
                #pragma unroll
                for (int q = 0; q < 8; ++q) p[q] += xv * wr[q];
            }
            #pragma unroll
            for (int q = 0; q < 8; ++q)
                #pragma unroll
                for (int o = 16; o; o >>= 1) p[q] += __shfl_down_sync(0xffffffffu, p[q], o);
            if (lane == 0) {
                ((float4*)g_es)[m] = make_float4(p[0], p[2], p[4], p[6]);
                ((float4*)g_ed)[m] = make_float4(p[1], p[3], p[5], p[7]);
            }
        }
    }
}

// ---------------- head GEMM ----------------
template<bool RELU, bool DECODE>
__global__ __launch_bounds__(256) void head_gemm_kernel(
    const void* __restrict__ Ain, const float* __restrict__ B,
    const float* __restrict__ bias, float* __restrict__ C,
    int M, int N, int K)
{
    __shared__ float As[32][33];
    __shared__ float Bs[32][33];
    int tid = threadIdx.x;
    int n0 = blockIdx.x*32, m0 = blockIdx.y*32;
    int ty = tid >> 4, tx = tid & 15;
    float a00 = 0.f, a01 = 0.f, a10 = 0.f, a11 = 0.f;
    for (int k0 = 0; k0 < K; k0 += 32) {
        {
            int r = tid >> 3, j = (tid & 7)*4;
            int gm = m0 + r;
            #pragma unroll
            for (int q = 0; q < 4; ++q) {
                int gk = k0 + j + q;
                float v = 0.f;
                if (gm < M && gk < K) {
                    if (DECODE) v = fmap_inv(((const unsigned*)Ain)[gm*K + gk]);
                    else        v = ((const float*)Ain)[gm*K + gk];
                }
                As[j + q][r] = v;
            }
            int kk = tid >> 3, jn = (tid & 7)*4;
            #pragma unroll
            for (int q = 0; q < 4; ++q) {
                int gn = n0 + jn + q;
                int gk = k0 + kk;
                Bs[kk][jn + q] = (gk < K && gn < N) ? B[(size_t)gk*N + gn] : 0.f;
            }
        }
        __syncthreads();
        #pragma unroll
        for (int k = 0; k < 32; ++k) {
            float av0 = As[k][2*ty], av1 = As[k][2*ty+1];
            float bv0 = Bs[k][2*tx], bv1 = Bs[k][2*tx+1];
            a00 += av0*bv0; a01 += av0*bv1;
            a10 += av1*bv0; a11 += av1*bv1;
        }
        __syncthreads();
    }
    int m = m0 + 2*ty, n = n0 + 2*tx;
    if (m < M && n < N) {
        float b0 = bias[n], b1 = bias[n+1];
        float v00 = a00 + b0, v01 = a01 + b1, v10 = a10 + b0, v11 = a11 + b1;
        if (RELU) { v00 = fmaxf(v00,0.f); v01 = fmaxf(v01,0.f); v10 = fmaxf(v10,0.f); v11 = fmaxf(v11,0.f); }
        C[(size_t)m*N + n] = v00; C[(size_t)m*N + n + 1] = v01;
        if (m + 1 < M) { C[(size_t)(m+1)*N + n] = v10; C[(size_t)(m+1)*N + n + 1] = v11; }
    }
}

// ---------------- launch ----------------
extern "C" void kernel_launch(void* const* d_in, const int* in_sizes, int n_in,
                              void* d_out, int out_size) {
    const float* x        = (const float*)d_in[0];
    const int*   ei       = (const int*)  d_in[1];
    const float* ew       = (const float*)d_in[2];
    const int*   batch    = (const int*)  d_in[3];
    const float* W_gcn    = (const float*)d_in[4];
    const float* b_gcn    = (const float*)d_in[5];
    const float* W_gat1   = (const float*)d_in[6];
    const float* a_src1   = (const float*)d_in[7];
    const float* a_dst1   = (const float*)d_in[8];
    const float* b_gat1   = (const float*)d_in[9];
    const float* W_gat2   = (const float*)d_in[10];
    const float* a_src2   = (const float*)d_in[11];
    const float* a_dst2   = (const float*)d_in[12];
    const float* b_gat2   = (const float*)d_in[13];
    const float* W_fc1    = (const float*)d_in[14];
    const float* b_fc1    = (const float*)d_in[15];
    const float* W_fc2    = (const float*)d_in[16];
    const float* b_fc2    = (const float*)d_in[17];
    const float* pro_bias = (const float*)d_in[18];
    const float* W_g1     = (const float*)d_in[19];
    const float* b_g1     = (const float*)d_in[20];
    const float* W_g2     = (const float*)d_in[21];
    const float* b_g2     = (const float*)d_in[22];
    float* out = (float*)d_out;

    float *p_h0, *p_x1, *p_x2, *p_Z, *p_hid, *p_bias_fc, *p_wesd1, *p_wesd2;
    float *p_wgcn, *p_ws1, *p_ws2, *p_wfc1, *p_wfc2;
    unsigned* p_pool_u;
    cudaGetSymbolAddress((void**)&p_h0,   g_h0);
    cudaGetSymbolAddress((void**)&p_x1,   g_x1);
    cudaGetSymbolAddress((void**)&p_x2,   g_x2);
    cudaGetSymbolAddress((void**)&p_Z,    g_Z);
    cudaGetSymbolAddress((void**)&p_hid,  g_hid);
    cudaGetSymbolAddress((void**)&p_bias_fc, g_bias_fc);
    cudaGetSymbolAddress((void**)&p_wesd1, g_wesd1);
    cudaGetSymbolAddress((void**)&p_wesd2, g_wesd2);
    cudaGetSymbolAddress((void**)&p_wgcn, g_wgcn);
    cudaGetSymbolAddress((void**)&p_ws1,  g_ws1);
    cudaGetSymbolAddress((void**)&p_ws2,  g_ws2);
    cudaGetSymbolAddress((void**)&p_wfc1, g_wfc1);
    cudaGetSymbolAddress((void**)&p_wfc2, g_wfc2);
    cudaGetSymbolAddress((void**)&p_pool_u, g_pool_u);

    static bool attr_done = false;
    if (!attr_done) {
        cudaFuncSetAttribute(gcn_gemm_kernel, cudaFuncAttributeMaxDynamicSharedMemorySize, SMEM_GEMM_BYTES);
        cudaFuncSetAttribute(fused_gat_kernel<1>, cudaFuncAttributeMaxDynamicSharedMemorySize, SMEM_FUSED_BYTES);
        cudaFuncSetAttribute(fused_gat_kernel<2>, cudaFuncAttributeMaxDynamicSharedMemorySize, SMEM_FUSED_BYTES);
        attr_done = true;
    }

    const int TB = 256;
    const int MT = (NN + 127)/128;   // 235
    dim3 ggrid(MT, 1);

    // slots 1-3 independent; slot 4 = GCN GEMM (profiled)
    prep_Wgcn_kernel<<<(NPAD*FIN+TB-1)/TB, TB>>>(W_gcn);
    zero_cnt_pool_kernel<<<(NN+TB-1)/TB, TB>>>();
    hist_kernel<<<(EE+TB-1)/TB, TB>>>(ei);
    gcn_gemm_kernel<<<ggrid, 256, SMEM_GEMM_BYTES>>>(x, p_wgcn, p_h0, NN, FIN);
    // CSR chain
    scan_kernel<<<1, 1024>>>();
    fill_kernel<<<(EE+TB-1)/TB, TB>>>(ei);
    deg_kernel<<<(NN*32+TB-1)/TB, TB>>>(ew);
    // weight prep
    prep_Wstack2_kernel<<<(2*NPAD*HH+TB-1)/TB, TB>>>(W_gat1, W_gat2);
    prep_Wfc12_kernel<<<(2*NPAD*HID+TB-1)/TB, TB>>>(W_fc1, W_fc2);
    prep_esd_bias_kernel<<<(2*HID*8+HID+TB-1)/TB, TB>>>(W_gat1, a_src1, a_dst1,
                                                        W_gat2, a_src2, a_dst2,
                                                        b_fc1, b_fc2, pro_bias);

    // layer 0: aggregate + layer-1 scores fused
    gcn_agg_kernel<<<NN, 160>>>(ew, b_gcn);

    // layer 1
    gat_aggz_kernel<<<NN, 160>>>(p_x1);
    fused_gat_kernel<1><<<ggrid, 256, SMEM_FUSED_BYTES>>>(p_Z, p_ws1, b_gat1, p_x1,
                                                          p_wfc1, p_wfc2, p_bias_fc, p_wesd2,
                                                          p_x2, nullptr, NN);

    // layer 2
    gat_aggz_kernel<<<NN, 160>>>(p_x2);
    fused_gat_kernel<2><<<ggrid, 256, SMEM_FUSED_BYTES>>>(p_Z, p_ws2, b_gat2, p_x2,
                                                          p_wfc1, p_wfc2, p_bias_fc, nullptr,
                                                          nullptr, batch, NN);

    // head
    head_gemm_kernel<true, true ><<<dim3(GFC/32, GG/32), 256>>>(p_pool_u, W_g1, b_g1, p_hid, GG, GFC, HID);
    head_gemm_kernel<false,false><<<dim3(OUTD/32, GG/32), 256>>>(p_hid, W_g2, b_g2, out, GG, OUTD, GFC);
}

// round 12
// speedup vs baseline: 1.2130x; 1.0482x over previous
#include <cuda_runtime.h>
#include <math.h>
#include <stdint.h>

// ---------------- problem constants ----------------
#define NN    30000
#define EE    300000
#define FIN   33
#define HID   132
#define HEADS 4
#define HH    528
#define GG    64
#define GFC   1024
#define OUTD  128
#define NPAD  144

// ---------------- scratch (device globals) ----------------
__device__ __align__(16) float g_dis[NN];
__device__ int   g_cnt[NN];
__device__ int   g_off[NN+1];
__device__ int   g_cur[NN];
__device__ int   g_csr_src[EE];
__device__ int   g_csr_eid[EE];
__device__ __align__(16) float g_h0[NN*HID];
__device__ __align__(16) float g_x1[NN*HID];
__device__ __align__(16) float g_x2[NN*HID];
__device__ __align__(16) float g_Z[NN*HH];
__device__ __align__(16) float g_es[NN*HEADS];
__device__ __align__(16) float g_ed[NN*HEADS];
__device__ unsigned g_pool_u[GG*HID];
__device__ __align__(16) float g_hid[GG*GFC];
__device__ __align__(16) float g_wesd1[HID*8];
__device__ __align__(16) float g_wesd2[HID*8];
__device__ __align__(16) float g_wgcn[NPAD*FIN];
__device__ __align__(16) float g_ws1[NPAD*HH];
__device__ __align__(16) float g_ws2[NPAD*HH];
__device__ __align__(16) float g_wfc1[NPAD*HID];
__device__ __align__(16) float g_wfc2[NPAD*HID];
__device__ float g_bias_fc[HID];

// ---------------- CSR build ----------------
__global__ void zero_cnt_pool_kernel() {
    int i = blockIdx.x*blockDim.x + threadIdx.x;
    if (i < NN) g_cnt[i] = 0;
    if (i < GG*HID) g_pool_u[i] = 0u;
}
__global__ void hist_kernel(const int* __restrict__ ei) {
    int e = blockIdx.x*blockDim.x + threadIdx.x;
    if (e < EE) atomicAdd(&g_cnt[ei[EE + e]], 1);
}
__global__ void scan_kernel() {
    const int CH = (NN + 1023) / 1024;
    __shared__ int ssum[1024];
    int t = threadIdx.x;
    int c0 = t*CH, c1 = min(c0+CH, NN);
    int s = 0;
    for (int i = c0; i < c1; ++i) s += g_cnt[i];
    ssum[t] = s;
    __syncthreads();
    for (int d = 1; d < 1024; d <<= 1) {
        int v = (t >= d) ? ssum[t-d] : 0;
        __syncthreads();
        ssum[t] += v;
        __syncthreads();
    }
    int run = (t == 0) ? 0 : ssum[t-1];
    for (int i = c0; i < c1; ++i) { g_off[i] = run; g_cur[i] = run; run += g_cnt[i]; }
    if (t == 0) g_off[NN] = ssum[1023];
}
__global__ void fill_kernel(const int* __restrict__ ei) {
    int e = blockIdx.x*blockDim.x + threadIdx.x;
    if (e >= EE) return;
    int d = ei[EE + e];
    int p = atomicAdd(&g_cur[d], 1);
    g_csr_src[p] = ei[e];
    g_csr_eid[p] = e;
}
__global__ void deg_kernel(const float* __restrict__ ew) {
    int gw = (blockIdx.x*blockDim.x + threadIdx.x) >> 5;
    int lane = threadIdx.x & 31;
    if (gw >= NN) return;
    int b0 = g_off[gw], b1 = g_off[gw+1];
    float s = 0.f;
    for (int j = b0 + lane; j < b1; j += 32) s += ew[g_csr_eid[j]];
    #pragma unroll
    for (int o = 16; o; o >>= 1) s += __shfl_down_sync(0xffffffffu, s, o);
    if (lane == 0) g_dis[gw] = rsqrtf(1.f + s);
}

// ---------------- weight prep ----------------
__global__ void prep_Wgcn_kernel(const float* __restrict__ W) {
    int i = blockIdx.x*blockDim.x + threadIdx.x;
    if (i >= NPAD*FIN) return;
    int n = i / FIN, k = i % FIN;
    g_wgcn[i] = (n < HID) ? W[k*HID + n] : 0.f;
}
__global__ void prep_Wstack2_kernel(const float* __restrict__ W1, const float* __restrict__ W2) {
    int i = blockIdx.x*blockDim.x + threadIdx.x;
    if (i >= 2*NPAD*HH) return;
    const float* W = (i < NPAD*HH) ? W1 : W2;
    float* out = (i < NPAD*HH) ? g_ws1 : g_ws2;
    int j = (i < NPAD*HH) ? i : i - NPAD*HH;
    int n = j / HH, k = j % HH;
    float v = 0.f;
    if (n < HID) {
        int h = k / HID, kk = k % HID;
        v = 0.25f * W[kk*HH + h*HID + n];
    }
    out[j] = v;
}
__global__ void prep_Wfc12_kernel(const float* __restrict__ W1, const float* __restrict__ W2) {
    int i = blockIdx.x*blockDim.x + threadIdx.x;
    if (i >= 2*NPAD*HID) return;
    const float* W = (i < NPAD*HID) ? W1 : W2;
    float* out = (i < NPAD*HID) ? g_wfc1 : g_wfc2;
    int j = (i < NPAD*HID) ? i : i - NPAD*HID;
    int n = j / HID, k = j % HID;
    out[j] = (n < HID) ? W[k*HID + n] : 0.f;
}
__global__ void prep_esd_bias_kernel(const float* __restrict__ W1,
                                     const float* __restrict__ as1, const float* __restrict__ ad1,
                                     const float* __restrict__ W2,
                                     const float* __restrict__ as2, const float* __restrict__ ad2,
                                     const float* __restrict__ b1, const float* __restrict__ b2,
                                     const float* __restrict__ pro) {
    int i = blockIdx.x*blockDim.x + threadIdx.x;
    if (i < 2*HID*8) {
        const float* W = (i < HID*8) ? W1 : W2;
        const float* as = (i < HID*8) ? as1 : as2;
        const float* ad = (i < HID*8) ? ad1 : ad2;
        float* out = (i < HID*8) ? g_wesd1 : g_wesd2;
        int j = (i < HID*8) ? i : i - HID*8;
        int k = j >> 3, q = j & 7, h = q >> 1;
        const float* a = (q & 1) ? ad : as;
        float s = 0.f;
        for (int c = 0; c < HID; ++c) s += W[k*HH + h*HID + c] * a[h*HID + c];
        out[j] = s;
    } else if (i < 2*HID*8 + HID) {
        int c = i - 2*HID*8;
        g_bias_fc[c] = b1[c] + b2[c] + pro[c];
    }
}

__device__ __forceinline__ float lrelu02(float v) { return v > 0.f ? v : 0.2f*v; }

// ---------------- GCN aggregation + fused layer-1 scores ----------------
__global__ __launch_bounds__(160) void gcn_agg_kernel(const float* __restrict__ ew,
                                                      const float* __restrict__ bias) {
    __shared__ float snorm[64];
    __shared__ int   ssrc[64];
    __shared__ float sx[HID];
    int n = blockIdx.x, tid = threadIdx.x;
    int b0 = g_off[n], b1 = g_off[n+1];
    int deg = b1 - b0;
    float dn = g_dis[n];
    if (tid < 64 && tid < deg) {
        int j = b0 + tid;
        int s = g_csr_src[j];
        snorm[tid] = g_dis[s] * ew[g_csr_eid[j]] * dn;
        ssrc[tid] = s;
    }
    __syncthreads();
    if (tid < HID) {
        float acc = bias[tid] + dn*dn*g_h0[n*HID + tid];
        int lim = min(deg, 64);
        for (int t = 0; t < lim; ++t)
            acc += snorm[t] * g_h0[ssrc[t]*HID + tid];
        for (int j = b0 + 64; j < b1; ++j) {
            int s = g_csr_src[j];
            acc += g_dis[s] * ew[g_csr_eid[j]] * dn * g_h0[s*HID + tid];
        }
        acc = fmaxf(acc, 0.f);
        g_x1[n*HID + tid] = acc;
        sx[tid] = acc;
    }
    __syncthreads();
    if (tid < 32) {
        float p[8] = {0,0,0,0,0,0,0,0};
        for (int c = tid; c < HID; c += 32) {
            float xv = sx[c];
            const float* wr = g_wesd1 + c*8;
            #pragma unroll
            for (int q = 0; q < 8; ++q) p[q] += xv * wr[q];
        }
        #pragma unroll
        for (int q = 0; q < 8; ++q)
            #pragma unroll
            for (int o = 16; o; o >>= 1) p[q] += __shfl_down_sync(0xffffffffu, p[q], o);
        if (tid == 0) {
            ((float4*)g_es)[n] = make_float4(p[0], p[2], p[4], p[6]);
            ((float4*)g_ed)[n] = make_float4(p[1], p[3], p[5], p[7]);
        }
    }
}

// ---------------- GAT aggregate-first ----------------
__global__ __launch_bounds__(160) void gat_aggz_kernel(const float* __restrict__ xin) {
    __shared__ float4 sexp[64];
    __shared__ int    ssrc[64];
    __shared__ float4 s_inv;
    __shared__ float4 s_selfw;
    int n = blockIdx.x, tid = threadIdx.x;
    int b0 = g_off[n], b1 = g_off[n+1];
    int deg = b1 - b0;
    float4 edn = ((float4*)g_ed)[n];
    if (tid < 64) {
        float4 v = make_float4(0.f, 0.f, 0.f, 0.f);
        int s = 0;
        if (tid < deg) {
            s = g_csr_src[b0 + tid];
            float4 e4 = ((float4*)g_es)[s];
            v.x = __expf(lrelu02(e4.x + edn.x));
            v.y = __expf(lrelu02(e4.y + edn.y));
            v.z = __expf(lrelu02(e4.z + edn.z));
            v.w = __expf(lrelu02(e4.w + edn.w));
        }
        sexp[tid] = v;
        ssrc[tid] = s;
    }
    __syncthreads();
    if (tid < 32) {
        float4 a = sexp[tid], b = sexp[tid + 32];
        float4 ds = make_float4(a.x + b.x, a.y + b.y, a.z + b.z, a.w + b.w);
        for (int j = b0 + 64 + tid; j < b1; j += 32) {
            int s = g_csr_src[j];
            float4 e4 = ((float4*)g_es)[s];
            ds.x += __expf(lrelu02(e4.x + edn.x));
            ds.y += __expf(lrelu02(e4.y + edn.y));
            ds.z += __expf(lrelu02(e4.z + edn.z));
            ds.w += __expf(lrelu02(e4.w + edn.w));
        }
        #pragma unroll
        for (int o = 16; o; o >>= 1) {
            ds.x += __shfl_down_sync(0xffffffffu, ds.x, o);
            ds.y += __shfl_down_sync(0xffffffffu, ds.y, o);
            ds.z += __shfl_down_sync(0xffffffffu, ds.z, o);
            ds.w += __shfl_down_sync(0xffffffffu, ds.w, o);
        }
        if (tid == 0) {
            float4 en = ((float4*)g_es)[n];
            float sx = __expf(lrelu02(en.x + edn.x));
            float sy = __expf(lrelu02(en.y + edn.y));
            float sz = __expf(lrelu02(en.z + edn.z));
            float sw = __expf(lrelu02(en.w + edn.w));
            float ix = 1.f/(ds.x + sx), iy = 1.f/(ds.y + sy);
            float iz = 1.f/(ds.z + sz), iw = 1.f/(ds.w + sw);
            s_inv = make_float4(ix, iy, iz, iw);
            s_selfw = make_float4(sx*ix, sy*iy, sz*iz, sw*iw);
        }
    }
    __syncthreads();
    float4 inv = s_inv;
    if (tid < 64) {
        float4 v = sexp[tid];
        v.x *= inv.x; v.y *= inv.y; v.z *= inv.z; v.w *= inv.w;
        sexp[tid] = v;
    }
    __syncthreads();
    if (tid < HID) {
        float4 sw = s_selfw;
        float xv0 = xin[n*HID + tid];
        float acc0 = sw.x*xv0, acc1 = sw.y*xv0, acc2 = sw.z*xv0, acc3 = sw.w*xv0;
        int lim = min(deg, 64);
        for (int t = 0; t < lim; ++t) {
            float xv = xin[ssrc[t]*HID + tid];
            float4 al = sexp[t];
            acc0 += al.x*xv; acc1 += al.y*xv; acc2 += al.z*xv; acc3 += al.w*xv;
        }
        for (int j = b0 + 64; j < b1; ++j) {
            int s = g_csr_src[j];
            float4 e4 = ((float4*)g_es)[s];
            float xv = xin[s*HID + tid];
            acc0 += __expf(lrelu02(e4.x + edn.x))*inv.x*xv;
            acc1 += __expf(lrelu02(e4.y + edn.y))*inv.y*xv;
            acc2 += __expf(lrelu02(e4.z + edn.z))*inv.z*xv;
            acc3 += __expf(lrelu02(e4.w + edn.w))*inv.w*xv;
        }
        float* zp = g_Z + (size_t)n*HH;
        zp[tid]         = acc0;
        zp[HID + tid]   = acc1;
        zp[2*HID + tid] = acc2;
        zp[3*HID + tid] = acc3;
    }
}

// ---------------- GEMM common ----------------
#define SAS 36
#define SMA (128*SAS)
#define SMB (NPAD*SAS)
#define SXC_FLOATS (128*HID)
#define SMEM_FUSED_BYTES ((SXC_FLOATS + SMA + SMB)*4)   // 106752

#define CP_A16(dst, src, sz) asm volatile("cp.async.ca.shared.global [%0], [%1], 16, %2;" :: "r"(dst), "l"(src), "r"(sz) : "memory")
#define CP_COMMIT() asm volatile("cp.async.commit_group;" ::: "memory")
#define CP_WAIT1()  asm volatile("cp.async.wait_group 1;" ::: "memory")
#define CP_WAIT0()  asm volatile("cp.async.wait_group 0;" ::: "memory")

__device__ __forceinline__ void mma_tf32(float* d, const uint32_t* a, const uint32_t* b) {
    asm volatile("mma.sync.aligned.m16n8k8.row.col.f32.tf32.tf32.f32 "
        "{%0,%1,%2,%3}, {%4,%5,%6,%7}, {%8,%9}, {%0,%1,%2,%3};"
        : "+f"(d[0]), "+f"(d[1]), "+f"(d[2]), "+f"(d[3])
        : "r"(a[0]), "r"(a[1]), "r"(a[2]), "r"(a[3]), "r"(b[0]), "r"(b[1]));
}
__device__ __forceinline__ unsigned fmap(float f) {
    unsigned u = __float_as_uint(f);
    return (u & 0x80000000u) ? ~u : (u | 0x80000000u);
}
__device__ __forceinline__ float fmap_inv(unsigned u) {
    return (u & 0x80000000u) ? __uint_as_float(u ^ 0x80000000u) : __uint_as_float(~u);
}

__device__ __forceinline__ void load_tile_async(
    float* sA, float* sB, const float* A1, const float* B,
    int m0, int k0, int M, int K, int tid)
{
    #pragma unroll
    for (int i = 0; i < 4; ++i) {
        int c = tid + i*256;
        int row = c >> 3, j = c & 7;
        int gm = m0 + row, gk = k0 + j*4;
        int sz = (gm < M && gk < K) ? 16 : 0;
        const float* src = sz ? A1 + (size_t)gm*K + gk : A1;
        uint32_t dst = (uint32_t)__cvta_generic_to_shared(sA + row*SAS + j*4);
        CP_A16(dst, src, sz);
    }
    #pragma unroll
    for (int i = 0; i < 5; ++i) {
        int c = tid + i*256;
        if (c >= NPAD*8) break;
        int row = c >> 3, j = c & 7;
        int gk = k0 + j*4;
        int sz = (gk < K) ? 16 : 0;
        const float* src = sz ? B + (size_t)row*K + gk : B;
        uint32_t dst = (uint32_t)__cvta_generic_to_shared(sB + row*SAS + j*4);
        CP_A16(dst, src, sz);
    }
}

__device__ __forceinline__ void gemm_mainloop_tri(
    float* smem, const float* A1, const float* B,
    int m0, int M, int K, int tid, int lane, int warpM, int warpN,
    float acc[2][9][4])
{
    float* sAbuf[2] = { smem, smem + SMA };
    float* sBbuf[2] = { smem + 2*SMA, smem + 2*SMA + SMB };
    int kt = (K + 31) >> 5;
    load_tile_async(sAbuf[0], sBbuf[0], A1, B, m0, 0, M, K, tid);
    CP_COMMIT();
    for (int t = 0; t < kt; ++t) {
        int s = t & 1;
        if (t + 1 < kt) {
            load_tile_async(sAbuf[s^1], sBbuf[s^1], A1, B, m0, (t+1)*32, M, K, tid);
            CP_COMMIT();
        }
        if (t + 1 < kt) CP_WAIT1(); else CP_WAIT0();
        __syncthreads();
        const float* cA = sAbuf[s];
        const float* cB = sBbuf[s];
        int gr = lane >> 2, gc = lane & 3;
        #pragma unroll
        for (int kk = 0; kk < 4; ++kk) {
            int c0 = kk*8 + gc;
            uint32_t ah[2][4], al[2][4];
            #pragma unroll
            for (int mt = 0; mt < 2; ++mt) {
                int r0 = warpM*32 + mt*16 + gr;
                float av[4];
                av[0] = cA[r0*SAS + c0];
                av[1] = cA[(r0+8)*SAS + c0];
                av[2] = cA[r0*SAS + c0 + 4];
                av[3] = cA[(r0+8)*SAS + c0 + 4];
                #pragma unroll
                for (int q = 0; q < 4; ++q) {
                    uint32_t h = __float_as_uint(av[q]) & 0xFFFFE000u;
                    ah[mt][q] = h;
                    al[mt][q] = __float_as_uint(av[q] - __uint_as_float(h));
                }
            }
            #pragma unroll
            for (int nt = 0; nt < 9; ++nt) {
                int n = warpN*72 + nt*8 + gr;
                float bv[2];
                bv[0] = cB[n*SAS + c0];
                bv[1] = cB[n*SAS + c0 + 4];
                uint32_t bh[2], bl[2];
                #pragma unroll
                for (int q = 0; q < 2; ++q) {
                    uint32_t h = __float_as_uint(bv[q]) & 0xFFFFE000u;
                    bh[q] = h;
                    bl[q] = __float_as_uint(bv[q] - __uint_as_float(h));
                }
                #pragma unroll
                for (int mt = 0; mt < 2; ++mt) {
                    mma_tf32(acc[mt][nt], ah[mt], bh);
                    mma_tf32(acc[mt][nt], ah[mt], bl);
                    mma_tf32(acc[mt][nt], al[mt], bh);
                }
            }
        }
        __syncthreads();
    }
}

// ---------------- specialized GCN GEMM: K=33, contiguous loads, TRI ----------------
__global__ __launch_bounds__(256, 2) void gcn_gemm2_kernel(
    const float* __restrict__ A, const float* __restrict__ B,
    float* __restrict__ C, int M)
{
    __shared__ __align__(16) float sA[128*FIN];   // stride 33 (odd -> conflict-free)
    __shared__ __align__(16) float sB[NPAD*FIN];
    int tid = threadIdx.x, lane = tid & 31, wid = tid >> 5;
    int warpM = wid & 3, warpN = wid >> 2;
    int m0 = blockIdx.x*128;
    int rows = min(128, M - m0);
    int nAfl = rows*FIN;
    // A: contiguous [m0*33 .. (m0+rows)*33) as float4 stream
    const float4* A4 = (const float4*)(A + (size_t)m0*FIN);
    for (int i = tid; i < (128*FIN)/4; i += 256) {
        float4 v = make_float4(0.f, 0.f, 0.f, 0.f);
        if ((i + 1)*4 <= nAfl) v = A4[i];
        else if (i*4 < nAfl) {
            const float* s = (const float*)A4 + i*4;
            float t[4] = {0.f, 0.f, 0.f, 0.f};
            for (int q = 0; q < nAfl - i*4; ++q) t[q] = s[q];
            v = make_float4(t[0], t[1], t[2], t[3]);
        }
        ((float4*)sA)[i] = v;
    }
    // B: whole 144x33 contiguous
    for (int i = tid; i < (NPAD*FIN)/4; i += 256)
        ((float4*)sB)[i] = ((const float4*)B)[i];
    __syncthreads();

    float acc[2][9][4];
    #pragma unroll
    for (int i = 0; i < 2; ++i)
        #pragma unroll
        for (int j = 0; j < 9; ++j)
            #pragma unroll
            for (int q = 0; q < 4; ++q) acc[i][j][q] = 0.f;

    int gr = lane >> 2, gc = lane & 3;
    #pragma unroll
    for (int kk = 0; kk < 5; ++kk) {
        int c0 = kk*8 + gc;
        bool full = (kk < 4);
        bool ok0 = full || (gc == 0);      // kk==4: only k=32 valid
        uint32_t ah[2][4], al[2][4];
        #pragma unroll
        for (int mt = 0; mt < 2; ++mt) {
            int r0 = warpM*32 + mt*16 + gr;
            float av[4];
            av[0] = ok0 ? sA[r0*FIN + c0] : 0.f;
            av[1] = ok0 ? sA[(r0+8)*FIN + c0] : 0.f;
            av[2] = full ? sA[r0*FIN + c0 + 4] : 0.f;
            av[3] = full ? sA[(r0+8)*FIN + c0 + 4] : 0.f;
            #pragma unroll
            for (int q = 0; q < 4; ++q) {
                uint32_t h = __float_as_uint(av[q]) & 0xFFFFE000u;
                ah[mt][q] = h;
                al[mt][q] = __float_as_uint(av[q] - __uint_as_float(h));
            }
        }
        #pragma unroll
        for (int nt = 0; nt < 9; ++nt) {
            int n = warpN*72 + nt*8 + gr;
            float bv[2];
            bv[0] = ok0 ? sB[n*FIN + c0] : 0.f;
            bv[1] = full ? sB[n*FIN + c0 + 4] : 0.f;
            uint32_t bh[2], bl[2];
            #pragma unroll
            for (int q = 0; q < 2; ++q) {
                uint32_t h = __float_as_uint(bv[q]) & 0xFFFFE000u;
                bh[q] = h;
                bl[q] = __float_as_uint(bv[q] - __uint_as_float(h));
            }
            #pragma unroll
            for (int mt = 0; mt < 2; ++mt) {
                mma_tf32(acc[mt][nt], ah[mt], bh);
                mma_tf32(acc[mt][nt], ah[mt], bl);
                mma_tf32(acc[mt][nt], al[mt], bh);
            }
        }
    }

    int gc2 = 2*gc;
    #pragma unroll
    for (int mt = 0; mt < 2; ++mt)
        #pragma unroll
        for (int nt = 0; nt < 9; ++nt) {
            int n = warpN*72 + nt*8 + gc2;
            if (n >= HID) continue;
            #pragma unroll
            for (int rr = 0; rr < 2; ++rr) {
                int m = m0 + warpM*32 + mt*16 + gr + rr*8;
                if (m >= M) continue;
                *(float2*)(C + (size_t)m*HID + n) =
                    make_float2(acc[mt][nt][rr*2+0], acc[mt][nt][rr*2+1]);
            }
        }
}

// ---------------- FUSED GAT transform + gate (+ next-layer scores) ----------------
template<int LAYER>
__global__ __launch_bounds__(256, 2) void fused_gat_kernel(
    const float* __restrict__ Z, const float* __restrict__ Wt,
    const float* __restrict__ bias_t,
    const float* __restrict__ xp,
    const float* __restrict__ W1, const float* __restrict__ W2,
    const float* __restrict__ bias_fc,
    const float* __restrict__ wesd_next,
    float* __restrict__ Cout, const int* __restrict__ batch, int M)
{
    extern __shared__ float smem[];
    int tid = threadIdx.x, lane = tid & 31, wid = tid >> 5;
    int warpM = wid & 3, warpN = wid >> 2;
    int m0 = blockIdx.x*128;
    int gr = lane >> 2, gc = lane & 3, gc2 = 2*gc;

    float acc[2][9][4];
    #pragma unroll
    for (int i = 0; i < 2; ++i)
        #pragma unroll
        for (int j = 0; j < 9; ++j)
            #pragma unroll
            for (int q = 0; q < 4; ++q) acc[i][j][q] = 0.f;

    gemm_mainloop_tri(smem, Z, Wt, m0, M, HH, tid, lane, warpM, warpN, acc);

    float* sxc = smem;
    #pragma unroll
    for (int mt = 0; mt < 2; ++mt)
        #pragma unroll
        for (int nt = 0; nt < 9; ++nt) {
            int n = warpN*72 + nt*8 + gc2;
            if (n >= HID) continue;
            float bx = bias_t[n], by = bias_t[n+1];
            #pragma unroll
            for (int rr = 0; rr < 2; ++rr) {
                int lm = warpM*32 + mt*16 + gr + rr*8;
                int m = m0 + lm;
                float v0 = acc[mt][nt][rr*2+0] + bx;
                float v1 = acc[mt][nt][rr*2+1] + by;
                if (LAYER == 1) { v0 = fmaxf(v0, 0.f); v1 = fmaxf(v1, 0.f); }
                if (m >= M) { v0 = 0.f; v1 = 0.f; }
                sxc[lm*HID + n]     = v0;
                sxc[lm*HID + n + 1] = v1;
            }
        }
    __syncthreads();

    float* s2A = smem + SXC_FLOATS;
    float* s2B = s2A + SMA;
    #pragma unroll
    for (int i = 0; i < 2; ++i)
        #pragma unroll
        for (int j = 0; j < 9; ++j)
            #pragma unroll
            for (int q = 0; q < 4; ++q) acc[i][j][q] = 0.f;

    for (int sub = 0; sub < 2; ++sub) {
        const float* Bsrc = sub ? W2 : W1;
        for (int t = 0; t < 5; ++t) {
            #pragma unroll
            for (int i = 0; i < 5; ++i) {
                int c = tid + i*256;
                if (c >= NPAD*8) break;
                int row = c >> 3, j = c & 7;
                int gk = t*32 + j*4;
                int sz = (gk < HID) ? 16 : 0;
                const float* src = sz ? Bsrc + (size_t)row*HID + gk : Bsrc;
                uint32_t dst = (uint32_t)__cvta_generic_to_shared(s2B + row*SAS + j*4);
                CP_A16(dst, src, sz);
            }
            if (sub == 1) {
                #pragma unroll
                for (int i = 0; i < 4; ++i) {
                    int c = tid + i*256;
                    int row = c >> 3, j = c & 7;
                    int gk = t*32 + j*4;
                    int gm = m0 + row;
                    int sz = (gm < M && gk < HID) ? 16 : 0;
                    const float* src = sz ? xp + (size_t)gm*HID + gk : xp;
                    uint32_t dst = (uint32_t)__cvta_generic_to_shared(s2A + row*SAS + j*4);
                    CP_A16(dst, src, sz);
                }
            }
            CP_COMMIT();
            CP_WAIT0();
            __syncthreads();

            int ks = (t < 4) ? 4 : 1;
            for (int kk = 0; kk < ks; ++kk) {
                int c0l = kk*8 + gc;
                uint32_t ah[2][4];
                #pragma unroll
                for (int mt = 0; mt < 2; ++mt) {
                    int r0 = warpM*32 + mt*16 + gr;
                    float av[4];
                    if (sub == 0) {
                        int col = t*32 + c0l;
                        int col2 = col + 4;
                        av[0] = (col  < HID) ? sxc[r0*HID + col]      : 0.f;
                        av[1] = (col  < HID) ? sxc[(r0+8)*HID + col]  : 0.f;
                        av[2] = (col2 < HID) ? sxc[r0*HID + col2]     : 0.f;
                        av[3] = (col2 < HID) ? sxc[(r0+8)*HID + col2] : 0.f;
                    } else {
                        av[0] = s2A[r0*SAS + c0l];
                        av[1] = s2A[(r0+8)*SAS + c0l];
                        av[2] = s2A[r0*SAS + c0l + 4];
                        av[3] = s2A[(r0+8)*SAS + c0l + 4];
                    }
                    #pragma unroll
                    for (int q = 0; q < 4; ++q) ah[mt][q] = __float_as_uint(av[q]);
                }
                #pragma unroll
                for (int nt = 0; nt < 9; ++nt) {
                    int n = warpN*72 + nt*8 + gr;
                    uint32_t bh[2];
                    bh[0] = __float_as_uint(s2B[n*SAS + c0l]);
                    bh[1] = __float_as_uint(s2B[n*SAS + c0l + 4]);
                    #pragma unroll
                    for (int mt = 0; mt < 2; ++mt)
                        mma_tf32(acc[mt][nt], ah[mt], bh);
                }
            }
            __syncthreads();
        }
    }

    if (LAYER == 1) {
        for (int i = tid; i < HID*8; i += 256) s2B[i] = wesd_next[i];
    }

    #pragma unroll
    for (int mt = 0; mt < 2; ++mt)
        #pragma unroll
        for (int nt = 0; nt < 9; ++nt) {
            int n = warpN*72 + nt*8 + gc2;
            if (n >= HID) continue;
            float bx = bias_fc[n], by = bias_fc[n+1];
            #pragma unroll
            for (int rr = 0; rr < 2; ++rr) {
                int lm = warpM*32 + mt*16 + gr + rr*8;
                int m = m0 + lm;
                if (m >= M) continue;
                float z0 = 1.f / (1.f + __expf(-(acc[mt][nt][rr*2+0] + bx)));
                float z1 = 1.f / (1.f + __expf(-(acc[mt][nt][rr*2+1] + by)));
                float xc0 = sxc[lm*HID + n],     xc1 = sxc[lm*HID + n + 1];
                float2 xp2 = *(const float2*)(xp + (size_t)m*HID + n);
                float o0 = z0*xc0 + (1.f - z0)*xp2.x;
                float o1 = z1*xc1 + (1.f - z1)*xp2.y;
                if (LAYER == 1) {
                    *(float2*)(Cout + (size_t)m*HID + n) = make_float2(o0, o1);
                    sxc[lm*HID + n]     = o0;
                    sxc[lm*HID + n + 1] = o1;
                } else {
                    int bi = batch[m];
                    atomicMax(&g_pool_u[bi*HID + n],     fmap(o0));
                    atomicMax(&g_pool_u[bi*HID + n + 1], fmap(o1));
                }
            }
        }

    if (LAYER == 1) {
        __syncthreads();
        for (int r = 0; r < 16; ++r) {
            int lm = wid*16 + r;
            int m = m0 + lm;
            if (m >= M) continue;
            float p[8] = {0,0,0,0,0,0,0,0};
            for (int c = lane; c < HID; c += 32) {
                float xv = sxc[lm*HID + c];
                const float* wr = s2B + c*8;
                #pragma unroll
                for (int q = 0; q < 8; ++q) p[q] += xv * wr[q];
            }
            #pragma unroll
            for (int q = 0; q < 8; ++q)
                #pragma unroll
                for (int o = 16; o; o >>= 1) p[q] += __shfl_down_sync(0xffffffffu, p[q], o);
            if (lane == 0) {
                ((float4*)g_es)[m] = make_float4(p[0], p[2], p[4], p[6]);
                ((float4*)g_ed)[m] = make_float4(p[1], p[3], p[5], p[7]);
            }
        }
    }
}

// ---------------- head GEMM ----------------
template<bool RELU, bool DECODE>
__global__ __launch_bounds__(256) void head_gemm_kernel(
    const void* __restrict__ Ain, const float* __restrict__ B,
    const float* __restrict__ bias, float* __restrict__ C,
    int M, int N, int K)
{
    __shared__ float As[32][33];
    __shared__ float Bs[32][33];
    int tid = threadIdx.x;
    int n0 = blockIdx.x*32, m0 = blockIdx.y*32;
    int ty = tid >> 4, tx = tid & 15;
    float a00 = 0.f, a01 = 0.f, a10 = 0.f, a11 = 0.f;
    for (int k0 = 0; k0 < K; k0 += 32) {
        {
            int r = tid >> 3, j = (tid & 7)*4;
            int gm = m0 + r;
            #pragma unroll
            for (int q = 0; q < 4; ++q) {
                int gk = k0 + j + q;
                float v = 0.f;
                if (gm < M && gk < K) {
                    if (DECODE) v = fmap_inv(((const unsigned*)Ain)[gm*K + gk]);
                    else        v = ((const float*)Ain)[gm*K + gk];
                }
                As[j + q][r] = v;
            }
            int kk = tid >> 3, jn = (tid & 7)*4;
            #pragma unroll
            for (int q = 0; q < 4; ++q) {
                int gn = n0 + jn + q;
                int gk = k0 + kk;
                Bs[kk][jn + q] = (gk < K && gn < N) ? B[(size_t)gk*N + gn] : 0.f;
            }
        }
        __syncthreads();
        #pragma unroll
        for (int k = 0; k < 32; ++k) {
            float av0 = As[k][2*ty], av1 = As[k][2*ty+1];
            float bv0 = Bs[k][2*tx], bv1 = Bs[k][2*tx+1];
            a00 += av0*bv0; a01 += av0*bv1;
            a10 += av1*bv0; a11 += av1*bv1;
        }
        __syncthreads();
    }
    int m = m0 + 2*ty, n = n0 + 2*tx;
    if (m < M && n < N) {
        float b0 = bias[n], b1 = bias[n+1];
        float v00 = a00 + b0, v01 = a01 + b1, v10 = a10 + b0, v11 = a11 + b1;
        if (RELU) { v00 = fmaxf(v00,0.f); v01 = fmaxf(v01,0.f); v10 = fmaxf(v10,0.f); v11 = fmaxf(v11,0.f); }
        C[(size_t)m*N + n] = v00; C[(size_t)m*N + n + 1] = v01;
        if (m + 1 < M) { C[(size_t)(m+1)*N + n] = v10; C[(size_t)(m+1)*N + n + 1] = v11; }
    }
}

// ---------------- launch ----------------
extern "C" void kernel_launch(void* const* d_in, const int* in_sizes, int n_in,
                              void* d_out, int out_size) {
    const float* x        = (const float*)d_in[0];
    const int*   ei       = (const int*)  d_in[1];
    const float* ew       = (const float*)d_in[2];
    const int*   batch    = (const int*)  d_in[3];
    const float* W_gcn    = (const float*)d_in[4];
    const float* b_gcn    = (const float*)d_in[5];
    const float* W_gat1   = (const float*)d_in[6];
    const float* a_src1   = (const float*)d_in[7];
    const float* a_dst1   = (const float*)d_in[8];
    const float* b_gat1   = (const float*)d_in[9];
    const float* W_gat2   = (const float*)d_in[10];
    const float* a_src2   = (const float*)d_in[11];
    const float* a_dst2   = (const float*)d_in[12];
    const float* b_gat2   = (const float*)d_in[13];
    const float* W_fc1    = (const float*)d_in[14];
    const float* b_fc1    = (const float*)d_in[15];
    const float* W_fc2    = (const float*)d_in[16];
    const float* b_fc2    = (const float*)d_in[17];
    const float* pro_bias = (const float*)d_in[18];
    const float* W_g1     = (const float*)d_in[19];
    const float* b_g1     = (const float*)d_in[20];
    const float* W_g2     = (const float*)d_in[21];
    const float* b_g2     = (const float*)d_in[22];
    float* out = (float*)d_out;

    float *p_h0, *p_x1, *p_x2, *p_Z, *p_hid, *p_bias_fc, *p_wesd1, *p_wesd2;
    float *p_wgcn, *p_ws1, *p_ws2, *p_wfc1, *p_wfc2;
    unsigned* p_pool_u;
    cudaGetSymbolAddress((void**)&p_h0,   g_h0);
    cudaGetSymbolAddress((void**)&p_x1,   g_x1);
    cudaGetSymbolAddress((void**)&p_x2,   g_x2);
    cudaGetSymbolAddress((void**)&p_Z,    g_Z);
    cudaGetSymbolAddress((void**)&p_hid,  g_hid);
    cudaGetSymbolAddress((void**)&p_bias_fc, g_bias_fc);
    cudaGetSymbolAddress((void**)&p_wesd1, g_wesd1);
    cudaGetSymbolAddress((void**)&p_wesd2, g_wesd2);
    cudaGetSymbolAddress((void**)&p_wgcn, g_wgcn);
    cudaGetSymbolAddress((void**)&p_ws1,  g_ws1);
    cudaGetSymbolAddress((void**)&p_ws2,  g_ws2);
    cudaGetSymbolAddress((void**)&p_wfc1, g_wfc1);
    cudaGetSymbolAddress((void**)&p_wfc2, g_wfc2);
    cudaGetSymbolAddress((void**)&p_pool_u, g_pool_u);

    static cudaStream_t s1 = nullptr, s2 = nullptr;
    static cudaEvent_t eF = nullptr, e1 = nullptr, e2 = nullptr;
    static bool attr_done = false;
    if (!attr_done) {
        cudaFuncSetAttribute(fused_gat_kernel<1>, cudaFuncAttributeMaxDynamicSharedMemorySize, SMEM_FUSED_BYTES);
        cudaFuncSetAttribute(fused_gat_kernel<2>, cudaFuncAttributeMaxDynamicSharedMemorySize, SMEM_FUSED_BYTES);
        cudaStreamCreateWithFlags(&s1, cudaStreamNonBlocking);
        cudaStreamCreateWithFlags(&s2, cudaStreamNonBlocking);
        cudaEventCreateWithFlags(&eF, cudaEventDisableTiming);
        cudaEventCreateWithFlags(&e1, cudaEventDisableTiming);
        cudaEventCreateWithFlags(&e2, cudaEventDisableTiming);
        attr_done = true;
    }

    const int TB = 256;
    const int MT = (NN + 127)/128;   // 235
    dim3 ggrid(MT, 1);

    // fork: branch1 = GCN weights + GEMM, branch2 = GAT/gate/score weight prep,
    //       main   = CSR build chain
    cudaEventRecord(eF, 0);
    cudaStreamWaitEvent(s1, eF, 0);
    cudaStreamWaitEvent(s2, eF, 0);

    prep_Wgcn_kernel<<<(NPAD*FIN+TB-1)/TB, TB, 0, s1>>>(W_gcn);
    gcn_gemm2_kernel<<<ggrid, 256, 0, s1>>>(x, p_wgcn, p_h0, NN);
    cudaEventRecord(e1, s1);

    prep_Wstack2_kernel<<<(2*NPAD*HH+TB-1)/TB, TB, 0, s2>>>(W_gat1, W_gat2);
    prep_Wfc12_kernel<<<(2*NPAD*HID+TB-1)/TB, TB, 0, s2>>>(W_fc1, W_fc2);
    prep_esd_bias_kernel<<<(2*HID*8+HID+TB-1)/TB, TB, 0, s2>>>(W_gat1, a_src1, a_dst1,
                                                               W_gat2, a_src2, a_dst2,
                                                               b_fc1, b_fc2, pro_bias);
    cudaEventRecord(e2, s2);

    zero_cnt_pool_kernel<<<(NN+TB-1)/TB, TB>>>();
    hist_kernel<<<(EE+TB-1)/TB, TB>>>(ei);
    scan_kernel<<<1, 1024>>>();
    fill_kernel<<<(EE+TB-1)/TB, TB>>>(ei);
    deg_kernel<<<(NN*32+TB-1)/TB, TB>>>(ew);

    // join
    cudaStreamWaitEvent(0, e1, 0);
    cudaStreamWaitEvent(0, e2, 0);

    // layer 0: aggregate + layer-1 scores fused
    gcn_agg_kernel<<<NN, 160>>>(ew, b_gcn);

    // layer 1
    gat_aggz_kernel<<<NN, 160>>>(p_x1);
    fused_gat_kernel<1><<<ggrid, 256, SMEM_FUSED_BYTES>>>(p_Z, p_ws1, b_gat1, p_x1,
                                                          p_wfc1, p_wfc2, p_bias_fc, p_wesd2,
                                                          p_x2, nullptr, NN);

    // layer 2
    gat_aggz_kernel<<<NN, 160>>>(p_x2);
    fused_gat_kernel<2><<<ggrid, 256, SMEM_FUSED_BYTES>>>(p_Z, p_ws2, b_gat2, p_x2,
                                                          p_wfc1, p_wfc2, p_bias_fc, nullptr,
                                                          nullptr, batch, NN);

    // head
    head_gemm_kernel<true, true ><<<dim3(GFC/32, GG/32), 256>>>(p_pool_u, W_g1, b_g1, p_hid, GG, GFC, HID);
    head_gemm_kernel<false,false><<<dim3(OUTD/32, GG/32), 256>>>(p_hid, W_g2, b_g2, out, GG, OUTD, GFC);
}